// round 12
// baseline (speedup 1.0000x reference)
#include <cuda_runtime.h>

#define NN 50000
#define EE 800000

typedef unsigned long long u64;

// ---------------- f32x2 helpers ----------------
__device__ __forceinline__ void fma2(u64 &c, u64 a, u64 b){
    asm("fma.rn.f32x2 %0, %1, %2, %0;" : "+l"(c) : "l"(a), "l"(b));
}
__device__ __forceinline__ u64 pack2(float x, float y){
    u64 r; asm("mov.b64 %0, {%1, %2};" : "=l"(r) : "f"(x), "f"(y)); return r;
}
__device__ __forceinline__ float2 unpack2(u64 v){
    float2 r; asm("mov.b64 {%0, %1}, %2;" : "=f"(r.x), "=f"(r.y) : "l"(v)); return r;
}
__device__ __forceinline__ float sigf(float x){ return 1.f/(1.f+__expf(-x)); }

// ---------------- scratch ----------------
__device__ float g_node_pre[(size_t)NN*64];
__device__ float g_nf_logit[(size_t)NN*3];
__device__ float g_prevp[NN];
__device__ float g_agg[(size_t)NN*64];
__device__ float g_contrib[(size_t)EE*64];
__device__ float g_message[(size_t)EE*64];
__device__ float g_m[(size_t)EE*64];
__device__ float g_x[(size_t)EE*64];
__device__ int   g_deg[NN];
__device__ int   g_rowptr[NN+1];
__device__ int   g_cursor[NN];
__device__ int   g_eid[EE];

#define DSM 50944            // gemm kernels: Xs 8320 + Ws 4352 + bs 64 floats
#define DSM_GRU 172032       // fused gru: Xs 8320 + Hs 8320 + Wall 26112 + bsm 256 floats
#define GRU_GRID 152
#define GRU_TILES 6250       // EE/128

// ---------------- GEMM core (register-lean): TE=128; warp w -> cols 16w..; lane -> edges lane+32j ----------------
template<int NJ>
__device__ __forceinline__ void gemm_core(const float* Xs, const float* Ws, const float* bs,
                                          int w, int lane, u64 (&acc)[NJ][8])
{
    const int c0 = w*16;
    #pragma unroll
    for (int j=0;j<NJ;j++)
        #pragma unroll
        for (int q=0;q<8;q++) acc[j][q]=pack2(bs[c0+2*q],bs[c0+2*q+1]);
    #pragma unroll 2
    for (int k=0;k<64;k++){
        u64 x2[NJ];
        #pragma unroll
        for (int j=0;j<NJ;j++){
            float xk = Xs[(lane+32*j)*65 + k];
            x2[j] = pack2(xk,xk);
        }
        const ulonglong2* wp=(const ulonglong2*)(Ws + k*68 + c0);
        #pragma unroll
        for (int q=0;q<4;q++){
            ulonglong2 wv = wp[q];
            #pragma unroll
            for (int j=0;j<NJ;j++){
                fma2(acc[j][2*q],   x2[j], wv.x);
                fma2(acc[j][2*q+1], x2[j], wv.y);
            }
        }
    }
}
template<int NJ>
__device__ __forceinline__ void acc_to_os(float* Os,int w,int lane,u64 (&acc)[NJ][8]){
    const int c0=w*16;
    #pragma unroll
    for (int j=0;j<NJ;j++){
        float* row=&Os[(lane+32*j)*65 + c0];
        #pragma unroll
        for (int q=0;q<8;q++){ float2 v=unpack2(acc[j][q]); row[2*q]=v.x; row[2*q+1]=v.y; }
    }
}

// ---------------- 8-col x 2-edge GEMM core for fused GRU ----------------
__device__ __forceinline__ void gemm8x2(const float* Xs, const float* Wm, int c0, int e0,
                                        u64 (&acc)[2][4])
{
    #pragma unroll 4
    for (int k=0;k<64;k++){
        u64 x2a, x2b;
        { float xk = Xs[e0*65 + k];       x2a = pack2(xk,xk); }
        { float xk = Xs[(e0+32)*65 + k];  x2b = pack2(xk,xk); }
        const ulonglong2* wp=(const ulonglong2*)(Wm + k*68 + c0);
        #pragma unroll
        for (int q=0;q<2;q++){
            ulonglong2 wv = wp[q];
            fma2(acc[0][2*q],   x2a, wv.x);
            fma2(acc[0][2*q+1], x2a, wv.y);
            fma2(acc[1][2*q],   x2b, wv.x);
            fma2(acc[1][2*q+1], x2b, wv.y);
        }
    }
}

// ---------------- CSR build ----------------
__global__ void __launch_bounds__(256) k_hist(const int* __restrict__ tgt){
    int e=blockIdx.x*256+threadIdx.x;
    atomicAdd(&g_deg[tgt[e]],1);
}
__global__ void __launch_bounds__(1024) k_scan(){
    __shared__ int wsum[32];
    __shared__ int carry_s;
    int t=threadIdx.x, lane=t&31, wid=t>>5;
    if (t==0){ g_rowptr[0]=0; carry_s=0; }
    __syncthreads();
    for (int base=0; base<NN; base+=1024){
        int i=base+t;
        int v=(i<NN)? g_deg[i] : 0;
        int s=v;
        #pragma unroll
        for (int o=1;o<32;o<<=1){ int u=__shfl_up_sync(0xffffffffu,s,o); if(lane>=o) s+=u; }
        if (lane==31) wsum[wid]=s;
        __syncthreads();
        if (wid==0){
            int ws=wsum[lane];
            #pragma unroll
            for (int o=1;o<32;o<<=1){ int u=__shfl_up_sync(0xffffffffu,ws,o); if(lane>=o) ws+=u; }
            wsum[lane]=ws;
        }
        __syncthreads();
        int off=(wid>0)? wsum[wid-1] : 0;
        int inc=s+off+carry_s;
        if (i<NN){ g_rowptr[i+1]=inc; g_cursor[i]=inc-v; }
        __syncthreads();
        if (t==1023) carry_s=inc;
        __syncthreads();
    }
}
__global__ void __launch_bounds__(256) k_fill(const int* __restrict__ tgt){
    int e=blockIdx.x*256+threadIdx.x;
    int p=atomicAdd(&g_cursor[tgt[e]],1);
    g_eid[p]=e;
}

// ---------------- segment sum by gather ----------------
__global__ void __launch_bounds__(256) k_gather(const float* __restrict__ S){
    int node=blockIdx.x*4+(threadIdx.x>>6);
    int f=threadIdx.x&63;
    int s=g_rowptr[node], e=g_rowptr[node+1];
    float a=0.f;
    for (int i=s;i<e;i++){
        int eid=__ldg(&g_eid[i]);
        a += __ldg(&S[(size_t)eid*64+f]);
    }
    g_agg[(size_t)node*64+f]=a;
}

// ---------------- per-node precompute ----------------
__global__ void __launch_bounds__(256) k_node(
    const float* __restrict__ prob, const float* __restrict__ seed,
    const float* __restrict__ W_node, const float* __restrict__ b_node,
    const float* __restrict__ W_init, const float* __restrict__ b_init,
    const float* __restrict__ W_out,  const float* __restrict__ b_out)
{
    __shared__ float Wi[4096];
    __shared__ float Wn0[64], Wn1[64], bn[64], bi[64], Wo[192], bo[3];
    int tid = threadIdx.x;
    for (int i=tid;i<4096;i+=256) Wi[i]=W_init[i];
    if (tid<64){ Wn0[tid]=W_node[tid]; Wn1[tid]=W_node[64+tid]; bn[tid]=b_node[tid]; bi[tid]=b_init[tid]; }
    for (int i=tid;i<192;i+=256) Wo[i]=W_out[192+i];
    if (tid<3) bo[tid]=b_out[tid];
    __syncthreads();
    int n = blockIdx.x*256 + tid;
    if (n >= NN) return;
    float p = prob[n], s = seed[n];
    u64 acc[32];
    #pragma unroll
    for (int j=0;j<32;j++) acc[j]=pack2(bi[2*j],bi[2*j+1]);
    float l0=bo[0], l1=bo[1], l2=bo[2];
    #pragma unroll 4
    for (int k=0;k<64;k++){
        float nf = fmaxf(fmaf(p,Wn0[k],fmaf(s,Wn1[k],bn[k])), 0.f);
        u64 x2 = pack2(nf,nf);
        const ulonglong2* wr = (const ulonglong2*)&Wi[k*64];
        #pragma unroll
        for (int q=0;q<16;q++){ ulonglong2 w=wr[q]; fma2(acc[2*q],x2,w.x); fma2(acc[2*q+1],x2,w.y); }
        l0 = fmaf(nf,Wo[k*3],l0); l1 = fmaf(nf,Wo[k*3+1],l1); l2 = fmaf(nf,Wo[k*3+2],l2);
    }
    float4* outp = (float4*)&g_node_pre[(size_t)n*64];
    #pragma unroll
    for (int q=0;q<16;q++){ float2 a=unpack2(acc[2*q]); float2 b=unpack2(acc[2*q+1]); outp[q]=make_float4(a.x,a.y,b.x,b.y); }
    g_nf_logit[n*3]=l0; g_nf_logit[n*3+1]=l1; g_nf_logit[n*3+2]=l2;
}

// ---------------- edge init (TE=128, NJ=4, 4 blocks/SM) ----------------
__global__ void __launch_bounds__(128,4) k_edge_init(
    const float* __restrict__ raw, const int* __restrict__ src,
    const float* __restrict__ W_edge, const float* __restrict__ b_edge,
    const float* __restrict__ W_init, const float* __restrict__ W_me)
{
    extern __shared__ float sm[];
    float* Xs=sm; float* Ws=sm+8320; float* bs=Ws+4352;
    __shared__ float we[64], be[64], rawv[128];
    __shared__ int srcs[128];
    int tid=threadIdx.x, w=tid>>5, lane=tid&31;
    size_t base=(size_t)blockIdx.x*128;
    if (tid<64){ we[tid]=W_edge[tid]; be[tid]=b_edge[tid]; bs[tid]=0.f; }
    rawv[tid]=raw[base+tid]; srcs[tid]=src[base+tid];
    for (int i=tid;i<4096;i+=128) Ws[(i>>6)*68+(i&63)]=W_init[4096+i];
    __syncthreads();
    for (int i=tid;i<8192;i+=128){ int e=i>>6,f=i&63; Xs[e*65+f]=fmaxf(fmaf(rawv[e],we[f],be[f]),0.f); }
    __syncthreads();
    u64 acc[4][8];
    gemm_core<4>(Xs,Ws,bs,w,lane,acc);
    __syncthreads();
    acc_to_os<4>(Xs,w,lane,acc);
    __syncthreads();
    for (int i=tid;i<8192;i+=128){
        int e=i>>6, f=i&63;
        float v=Xs[e*65+f] + __ldg(&g_node_pre[(size_t)srcs[e]*64+f]);
        g_message[base*64+i]=fmaxf(v,0.f);
    }
    __syncthreads();
    for (int i=tid;i<4096;i+=128) Ws[(i>>6)*68+(i&63)]=W_me[4096+i];
    __syncthreads();
    for (int i=tid;i<8192;i+=128){ int e=i>>6,f=i&63; Xs[e*65+f]=fmaxf(fmaf(rawv[e],we[f],be[f]),0.f); }
    __syncthreads();
    gemm_core<4>(Xs,Ws,bs,w,lane,acc);
    __syncthreads();
    acc_to_os<4>(Xs,w,lane,acc);
    __syncthreads();
    for (int i=tid;i<8192;i+=128) g_contrib[base*64+i]=Xs[(i>>6)*65+(i&63)];
}

// ---------------- m = relu(message @ W_me[0:64] + contrib + b_me) ----------------
__global__ void __launch_bounds__(128,4) k_me(const float* __restrict__ W, const float* __restrict__ b)
{
    extern __shared__ float sm[];
    float* Xs=sm; float* Ws=sm+8320; float* bs=Ws+4352;
    int tid=threadIdx.x, w=tid>>5, lane=tid&31;
    size_t base=(size_t)blockIdx.x*128;
    for (int i=tid;i<4096;i+=128) Ws[(i>>6)*68+(i&63)]=W[i];
    if (tid<64) bs[tid]=b[tid];
    for (int i=tid;i<8192;i+=128) Xs[(i>>6)*65+(i&63)]=g_message[base*64+i];
    __syncthreads();
    u64 acc[4][8];
    gemm_core<4>(Xs,Ws,bs,w,lane,acc);
    __syncthreads();
    acc_to_os<4>(Xs,w,lane,acc);
    __syncthreads();
    for (int i=tid;i<8192;i+=128){
        float v=Xs[(i>>6)*65+(i&63)] + g_contrib[base*64+i];
        g_m[base*64+i]=fmaxf(v,0.f);
    }
}

// ---------------- x = relu((agg[src] - m[rev]) @ W_mp + b_mp) ----------------
__global__ void __launch_bounds__(128,4) k_mp(
    const float* __restrict__ W, const float* __restrict__ b,
    const int* __restrict__ src, const int* __restrict__ rev)
{
    extern __shared__ float sm[];
    float* Xs=sm; float* Ws=sm+8320; float* bs=Ws+4352;
    __shared__ int srcs[128], revs[128];
    int tid=threadIdx.x, w=tid>>5, lane=tid&31;
    size_t base=(size_t)blockIdx.x*128;
    srcs[tid]=src[base+tid]; revs[tid]=rev[base+tid];
    for (int i=tid;i<4096;i+=128) Ws[(i>>6)*68+(i&63)]=W[i];
    if (tid<64) bs[tid]=b[tid];
    __syncthreads();
    for (int i=tid;i<8192;i+=128){
        int e=i>>6, f=i&63;
        Xs[e*65+f] = __ldg(&g_agg[(size_t)srcs[e]*64+f]) - __ldg(&g_m[(size_t)revs[e]*64+f]);
    }
    __syncthreads();
    u64 acc[4][8];
    gemm_core<4>(Xs,Ws,bs,w,lane,acc);
    __syncthreads();
    acc_to_os<4>(Xs,w,lane,acc);
    __syncthreads();
    for (int i=tid;i<8192;i+=128) g_x[base*64+i]=fmaxf(Xs[(i>>6)*65+(i&63)],0.f);
}

// ---------------- fused gates + GRU (persistent, 512 threads, weights resident, z in regs) ----------------
// smem: Xs[8320] Hs[8320] Wall[6*4352] bsm[256]
__global__ void __launch_bounds__(512,1) k_grufuse(
    const float* __restrict__ Wih, const float* __restrict__ bih,
    const float* __restrict__ Whh, const float* __restrict__ bhh)
{
    extern __shared__ float sm[];
    float* Xs  = sm;
    float* Hs  = sm + 8320;
    float* Wall= sm + 16640;
    float* bsm = sm + 42752;
    int tid=threadIdx.x, w=tid>>5, lane=tid&31;
    const int c0 = (w&7)*8;
    const int e0 = (w>>3)*64 + lane;   // edges e0, e0+32

    for (int i=tid;i<24576;i+=512){
        int m=i>>12, r=i&4095, c=r>>6, k=r&63;
        const float* Wsrc = (m<3)? Wih : Whh;
        int g = (m<3)? m : (m-3);
        Wall[m*4352 + k*68 + c] = Wsrc[(size_t)(g*64+c)*64 + k];
    }
    if (tid<64){
        bsm[tid]     = bih[tid]     + bhh[tid];       // r
        bsm[64+tid]  = bih[64+tid]  + bhh[64+tid];    // z
        bsm[128+tid] = bih[128+tid];                  // in
        bsm[192+tid] = bhh[128+tid];                  // hn
    }
    __syncthreads();

    for (int t=blockIdx.x; t<GRU_TILES; t+=gridDim.x){
        size_t base=(size_t)t*128;
        for (int i=tid;i<8192;i+=512){
            int e=i>>6, f=i&63;
            Xs[e*65+f]=__ldg(&g_x[base*64+i]);
            Hs[e*65+f]=__ldg(&g_message[base*64+i]);
        }
        __syncthreads();

        u64 acc[2][4];
        float rr[16], zz[16];
        // pass r
        #pragma unroll
        for (int j=0;j<2;j++)
            #pragma unroll
            for (int q=0;q<4;q++) acc[j][q]=pack2(bsm[c0+2*q],bsm[c0+2*q+1]);
        gemm8x2(Xs, Wall+0*4352, c0, e0, acc);
        gemm8x2(Hs, Wall+3*4352, c0, e0, acc);
        #pragma unroll
        for (int j=0;j<2;j++)
            #pragma unroll
            for (int q=0;q<4;q++){
                float2 v=unpack2(acc[j][q]);
                rr[j*8+2*q]=sigf(v.x); rr[j*8+2*q+1]=sigf(v.y);
            }
        // pass z (kept in registers)
        #pragma unroll
        for (int j=0;j<2;j++)
            #pragma unroll
            for (int q=0;q<4;q++) acc[j][q]=pack2(bsm[64+c0+2*q],bsm[64+c0+2*q+1]);
        gemm8x2(Xs, Wall+1*4352, c0, e0, acc);
        gemm8x2(Hs, Wall+4*4352, c0, e0, acc);
        #pragma unroll
        for (int j=0;j<2;j++)
            #pragma unroll
            for (int q=0;q<4;q++){
                float2 v=unpack2(acc[j][q]);
                zz[j*8+2*q]=sigf(v.x); zz[j*8+2*q+1]=sigf(v.y);
            }
        // pass n (two accumulator sets)
        u64 accI[2][4], accH[2][4];
        #pragma unroll
        for (int j=0;j<2;j++)
            #pragma unroll
            for (int q=0;q<4;q++){
                accI[j][q]=pack2(bsm[128+c0+2*q],bsm[128+c0+2*q+1]);
                accH[j][q]=pack2(bsm[192+c0+2*q],bsm[192+c0+2*q+1]);
            }
        gemm8x2(Xs, Wall+2*4352, c0, e0, accI);
        gemm8x2(Hs, Wall+5*4352, c0, e0, accH);
        // combine GRU into registers — no smem writes yet
        #pragma unroll
        for (int j=0;j<2;j++){
            int e=e0+32*j;
            #pragma unroll
            for (int q=0;q<4;q++){
                float2 iv=unpack2(accI[j][q]);
                float2 hv=unpack2(accH[j][q]);
                int cA=c0+2*q, cB=cA+1;
                float nA=tanhf(iv.x + rr[j*8+2*q]  *hv.x);
                float nB=tanhf(iv.y + rr[j*8+2*q+1]*hv.y);
                float zA=zz[j*8+2*q], zB=zz[j*8+2*q+1];
                float hA=Hs[e*65+cA], hB=Hs[e*65+cB];
                accI[j][q]=pack2((1.f-zA)*nA+zA*hA, (1.f-zB)*nB+zB*hB);
            }
        }
        __syncthreads();   // ALL reads of Xs/Hs complete before any write
        #pragma unroll
        for (int j=0;j<2;j++){
            int e=e0+32*j;
            #pragma unroll
            for (int q=0;q<4;q++){
                float2 o=unpack2(accI[j][q]);
                Hs[e*65+c0+2*q]  =o.x;
                Hs[e*65+c0+2*q+1]=o.y;
            }
        }
        __syncthreads();
        for (int i=tid;i<8192;i+=512) g_message[base*64+i]=Hs[(i>>6)*65+(i&63)];
        __syncthreads();
    }
}

// ---------------- nodes_out ----------------
__global__ void __launch_bounds__(256) k_nodes_out(
    int iter, float* __restrict__ outM, float* __restrict__ outD,
    const float* __restrict__ Wagg, const float* __restrict__ bagg,
    const float* __restrict__ Wout)
{
    __shared__ float Wa[4096]; __shared__ float ba[64]; __shared__ float Wo[192];
    int tid=threadIdx.x;
    for (int i=tid;i<4096;i+=256) Wa[i]=Wagg[i];
    if (tid<64) ba[tid]=bagg[tid];
    for (int i=tid;i<192;i+=256) Wo[i]=Wout[i];
    __syncthreads();
    int n=blockIdx.x*256+tid;
    if (n>=NN) return;
    float af[64];
    const float4* ar=(const float4*)&g_agg[(size_t)n*64];
    #pragma unroll
    for (int q=0;q<16;q++){ float4 v=ar[q]; af[4*q]=v.x; af[4*q+1]=v.y; af[4*q+2]=v.z; af[4*q+3]=v.w; }
    u64 acc[32];
    #pragma unroll
    for (int j=0;j<32;j++) acc[j]=pack2(ba[2*j],ba[2*j+1]);
    #pragma unroll 4
    for (int k=0;k<64;k++){
        u64 x2=pack2(af[k],af[k]);
        const ulonglong2* wr=(const ulonglong2*)&Wa[k*64];
        #pragma unroll
        for (int q=0;q<16;q++){ ulonglong2 w=wr[q]; fma2(acc[2*q],x2,w.x); fma2(acc[2*q+1],x2,w.y); }
    }
    float l0=0.f,l1=0.f,l2=0.f;
    #pragma unroll
    for (int j=0;j<32;j++){
        float2 v=unpack2(acc[j]);
        float a0=fmaxf(v.x,0.f), a1=fmaxf(v.y,0.f);
        int k0=2*j, k1=2*j+1;
        l0 += a0*Wo[k0*3+0] + a1*Wo[k1*3+0];
        l1 += a0*Wo[k0*3+1] + a1*Wo[k1*3+1];
        l2 += a0*Wo[k0*3+2] + a1*Wo[k1*3+2];
    }
    l0=fmaxf(l0+g_nf_logit[n*3+0],0.f);
    l1=fmaxf(l1+g_nf_logit[n*3+1],0.f);
    l2=fmaxf(l2+g_nf_logit[n*3+2],0.f);
    float mx=fmaxf(l0,fmaxf(l1,l2));
    float e0=expf(l0-mx), e1=expf(l1-mx), e2=expf(l2-mx);
    float sum=e0+e1+e2, ls=logf(sum);
    size_t ob=(size_t)iter*((size_t)NN*3)+(size_t)n*3;
    outM[ob+0]=l0-mx-ls; outM[ob+1]=l1-mx-ls; outM[ob+2]=l2-mx-ls;
    float p2=e2/sum;
    if (iter>0){
        float d=fabsf(p2-g_prevp[n]);
        atomicMax((int*)&outD[iter-1], __float_as_int(d));
    }
    g_prevp[n]=p2;
}

// ---------------- host ----------------
extern "C" void kernel_launch(void* const* d_in, const int* in_sizes, int n_in,
                              void* d_out, int out_size)
{
    const int*   src  = (const int*)  d_in[0];
    const int*   tgt  = (const int*)  d_in[1];
    const int*   rev  = (const int*)  d_in[2];
    const float* raw  = (const float*)d_in[3];
    const float* prob = (const float*)d_in[4];
    const float* seed = (const float*)d_in[5];
    const float* W_node=(const float*)d_in[6],  *b_node=(const float*)d_in[7];
    const float* W_edge=(const float*)d_in[8],  *b_edge=(const float*)d_in[9];
    const float* W_init=(const float*)d_in[10], *b_init=(const float*)d_in[11];
    const float* W_aggr=(const float*)d_in[12], *b_aggr=(const float*)d_in[13];
    const float* W_out =(const float*)d_in[14], *b_out =(const float*)d_in[15];
    const float* W_me  =(const float*)d_in[16], *b_me  =(const float*)d_in[17];
    const float* W_mp  =(const float*)d_in[18], *b_mp  =(const float*)d_in[19];
    const float* W_ih  =(const float*)d_in[20], *W_hh  =(const float*)d_in[21];
    const float* b_ih  =(const float*)d_in[22], *b_hh  =(const float*)d_in[23];

    float* outM = (float*)d_out;
    float* outD = (float*)d_out + (size_t)5*NN*3;

    cudaFuncSetAttribute(k_edge_init, cudaFuncAttributeMaxDynamicSharedMemorySize, DSM);
    cudaFuncSetAttribute(k_me,        cudaFuncAttributeMaxDynamicSharedMemorySize, DSM);
    cudaFuncSetAttribute(k_mp,        cudaFuncAttributeMaxDynamicSharedMemorySize, DSM);
    cudaFuncSetAttribute(k_grufuse,   cudaFuncAttributeMaxDynamicSharedMemorySize, DSM_GRU);

    void *degPtr=0, *msgPtr=0, *mPtr=0;
    cudaGetSymbolAddress(&degPtr, g_deg);
    cudaGetSymbolAddress(&msgPtr, g_message);
    cudaGetSymbolAddress(&mPtr,   g_m);

    // launch order: #6 = k_edge_init (ncu -s 5 -c 1 captures it)
    cudaMemsetAsync(degPtr, 0, NN*sizeof(int));                                             // 1
    cudaMemsetAsync(outD, 0, 4*sizeof(float));                                              // 2
    k_hist<<<EE/256,256>>>(tgt);                                                            // 3
    k_scan<<<1,1024>>>();                                                                   // 4
    k_node<<<(NN+255)/256,256>>>(prob, seed, W_node, b_node, W_init, b_init, W_out, b_out); // 5
    k_edge_init<<<EE/128,128,DSM>>>(raw, src, W_edge, b_edge, W_init, W_me);                // 6 (captured)
    k_fill<<<EE/256,256>>>(tgt);                                                            // 7

    k_gather<<<NN/4,256>>>((const float*)msgPtr);
    k_nodes_out<<<(NN+255)/256,256>>>(0, outM, outD, W_aggr, b_aggr, W_out);

    for (int l=0; l<4; l++){
        k_me<<<EE/128,128,DSM>>>(W_me, b_me);
        k_gather<<<NN/4,256>>>((const float*)mPtr);
        k_mp<<<EE/128,128,DSM>>>(W_mp, b_mp, src, rev);
        k_grufuse<<<GRU_GRID,512,DSM_GRU>>>(W_ih, b_ih, W_hh, b_hh);
        k_gather<<<NN/4,256>>>((const float*)msgPtr);
        k_nodes_out<<<(NN+255)/256,256>>>(l+1, outM, outD, W_aggr, b_aggr, W_out);
    }
}

// round 13
// speedup vs baseline: 1.0487x; 1.0487x over previous
#include <cuda_runtime.h>

#define NN 50000
#define EE 800000

typedef unsigned long long u64;

// ---------------- f32x2 helpers ----------------
__device__ __forceinline__ void fma2(u64 &c, u64 a, u64 b){
    asm("fma.rn.f32x2 %0, %1, %2, %0;" : "+l"(c) : "l"(a), "l"(b));
}
__device__ __forceinline__ u64 pack2(float x, float y){
    u64 r; asm("mov.b64 %0, {%1, %2};" : "=l"(r) : "f"(x), "f"(y)); return r;
}
__device__ __forceinline__ float2 unpack2(u64 v){
    float2 r; asm("mov.b64 {%0, %1}, %2;" : "=f"(r.x), "=f"(r.y) : "l"(v)); return r;
}
__device__ __forceinline__ float sigf(float x){ return 1.f/(1.f+__expf(-x)); }

// ---------------- scratch ----------------
__device__ float g_node_pre[(size_t)NN*64];
__device__ float g_nf_logit[(size_t)NN*3];
__device__ float g_prevp[NN];
__device__ float g_agg[(size_t)NN*64];
__device__ float g_contrib[(size_t)EE*64];
__device__ float g_message[(size_t)EE*64];
__device__ float g_m[(size_t)EE*64];
__device__ float g_x[(size_t)EE*64];
__device__ int   g_deg[NN];
__device__ int   g_rowptr[NN+1];
__device__ int   g_cursor[NN];
__device__ int   g_eid[EE];

#define DSM 50944            // gemm kernels: Xs 8320 + Ws 4352 + bs 64 floats
#define DSM_GRU 204800       // fused gru: Xs 8320 + Hs 8320 + Wall 26112 + Zs 8192 + bsm 256 floats
#define GRU_GRID 152
#define GRU_TILES 6250       // EE/128

// ---------------- GEMM core (register-lean, R11-proven): TE=128 ----------------
template<int NJ>
__device__ __forceinline__ void gemm_core(const float* Xs, const float* Ws, const float* bs,
                                          int w, int lane, u64 (&acc)[NJ][8])
{
    const int c0 = w*16;
    #pragma unroll
    for (int j=0;j<NJ;j++)
        #pragma unroll
        for (int q=0;q<8;q++) acc[j][q]=pack2(bs[c0+2*q],bs[c0+2*q+1]);
    #pragma unroll 2
    for (int k=0;k<64;k++){
        u64 x2[NJ];
        #pragma unroll
        for (int j=0;j<NJ;j++){
            float xk = Xs[(lane+32*j)*65 + k];
            x2[j] = pack2(xk,xk);
        }
        const ulonglong2* wp=(const ulonglong2*)(Ws + k*68 + c0);
        #pragma unroll
        for (int q=0;q<4;q++){
            ulonglong2 wv = wp[q];
            #pragma unroll
            for (int j=0;j<NJ;j++){
                fma2(acc[j][2*q],   x2[j], wv.x);
                fma2(acc[j][2*q+1], x2[j], wv.y);
            }
        }
    }
}
template<int NJ>
__device__ __forceinline__ void acc_to_os(float* Os,int w,int lane,u64 (&acc)[NJ][8]){
    const int c0=w*16;
    #pragma unroll
    for (int j=0;j<NJ;j++){
        float* row=&Os[(lane+32*j)*65 + c0];
        #pragma unroll
        for (int q=0;q<8;q++){ float2 v=unpack2(acc[j][q]); row[2*q]=v.x; row[2*q+1]=v.y; }
    }
}

// ---------------- 8-col x 2-edge GEMM core for fused GRU ----------------
__device__ __forceinline__ void gemm8x2(const float* Xs, const float* Wm, int c0, int e0,
                                        u64 (&acc)[2][4])
{
    #pragma unroll 4
    for (int k=0;k<64;k++){
        u64 x2a, x2b;
        { float xk = Xs[e0*65 + k];       x2a = pack2(xk,xk); }
        { float xk = Xs[(e0+32)*65 + k];  x2b = pack2(xk,xk); }
        const ulonglong2* wp=(const ulonglong2*)(Wm + k*68 + c0);
        #pragma unroll
        for (int q=0;q<2;q++){
            ulonglong2 wv = wp[q];
            fma2(acc[0][2*q],   x2a, wv.x);
            fma2(acc[0][2*q+1], x2a, wv.y);
            fma2(acc[1][2*q],   x2b, wv.x);
            fma2(acc[1][2*q+1], x2b, wv.y);
        }
    }
}

// ---------------- CSR build ----------------
__global__ void __launch_bounds__(256) k_hist(const int* __restrict__ tgt){
    int e=blockIdx.x*256+threadIdx.x;
    atomicAdd(&g_deg[tgt[e]],1);
}
__global__ void __launch_bounds__(1024) k_scan(){
    __shared__ int wsum[32];
    __shared__ int carry_s;
    int t=threadIdx.x, lane=t&31, wid=t>>5;
    if (t==0){ g_rowptr[0]=0; carry_s=0; }
    __syncthreads();
    for (int base=0; base<NN; base+=1024){
        int i=base+t;
        int v=(i<NN)? g_deg[i] : 0;
        int s=v;
        #pragma unroll
        for (int o=1;o<32;o<<=1){ int u=__shfl_up_sync(0xffffffffu,s,o); if(lane>=o) s+=u; }
        if (lane==31) wsum[wid]=s;
        __syncthreads();
        if (wid==0){
            int ws=wsum[lane];
            #pragma unroll
            for (int o=1;o<32;o<<=1){ int u=__shfl_up_sync(0xffffffffu,ws,o); if(lane>=o) ws+=u; }
            wsum[lane]=ws;
        }
        __syncthreads();
        int off=(wid>0)? wsum[wid-1] : 0;
        int inc=s+off+carry_s;
        if (i<NN){ g_rowptr[i+1]=inc; g_cursor[i]=inc-v; }
        __syncthreads();
        if (t==1023) carry_s=inc;
        __syncthreads();
    }
}
__global__ void __launch_bounds__(256) k_fill(const int* __restrict__ tgt){
    int e=blockIdx.x*256+threadIdx.x;
    int p=atomicAdd(&g_cursor[tgt[e]],1);
    g_eid[p]=e;
}

// ---------------- segment sum by gather ----------------
__global__ void __launch_bounds__(256) k_gather(const float* __restrict__ S){
    int node=blockIdx.x*4+(threadIdx.x>>6);
    int f=threadIdx.x&63;
    int s=g_rowptr[node], e=g_rowptr[node+1];
    float a=0.f;
    for (int i=s;i<e;i++){
        int eid=__ldg(&g_eid[i]);
        a += __ldg(&S[(size_t)eid*64+f]);
    }
    g_agg[(size_t)node*64+f]=a;
}

// ---------------- per-node precompute ----------------
__global__ void __launch_bounds__(256) k_node(
    const float* __restrict__ prob, const float* __restrict__ seed,
    const float* __restrict__ W_node, const float* __restrict__ b_node,
    const float* __restrict__ W_init, const float* __restrict__ b_init,
    const float* __restrict__ W_out,  const float* __restrict__ b_out)
{
    __shared__ float Wi[4096];
    __shared__ float Wn0[64], Wn1[64], bn[64], bi[64], Wo[192], bo[3];
    int tid = threadIdx.x;
    for (int i=tid;i<4096;i+=256) Wi[i]=W_init[i];
    if (tid<64){ Wn0[tid]=W_node[tid]; Wn1[tid]=W_node[64+tid]; bn[tid]=b_node[tid]; bi[tid]=b_init[tid]; }
    for (int i=tid;i<192;i+=256) Wo[i]=W_out[192+i];
    if (tid<3) bo[tid]=b_out[tid];
    __syncthreads();
    int n = blockIdx.x*256 + tid;
    if (n >= NN) return;
    float p = prob[n], s = seed[n];
    u64 acc[32];
    #pragma unroll
    for (int j=0;j<32;j++) acc[j]=pack2(bi[2*j],bi[2*j+1]);
    float l0=bo[0], l1=bo[1], l2=bo[2];
    #pragma unroll 4
    for (int k=0;k<64;k++){
        float nf = fmaxf(fmaf(p,Wn0[k],fmaf(s,Wn1[k],bn[k])), 0.f);
        u64 x2 = pack2(nf,nf);
        const ulonglong2* wr = (const ulonglong2*)&Wi[k*64];
        #pragma unroll
        for (int q=0;q<16;q++){ ulonglong2 w=wr[q]; fma2(acc[2*q],x2,w.x); fma2(acc[2*q+1],x2,w.y); }
        l0 = fmaf(nf,Wo[k*3],l0); l1 = fmaf(nf,Wo[k*3+1],l1); l2 = fmaf(nf,Wo[k*3+2],l2);
    }
    float4* outp = (float4*)&g_node_pre[(size_t)n*64];
    #pragma unroll
    for (int q=0;q<16;q++){ float2 a=unpack2(acc[2*q]); float2 b=unpack2(acc[2*q+1]); outp[q]=make_float4(a.x,a.y,b.x,b.y); }
    g_nf_logit[n*3]=l0; g_nf_logit[n*3+1]=l1; g_nf_logit[n*3+2]=l2;
}

// ---------------- edge init (TE=128, NJ=4, 4 blocks/SM) ----------------
__global__ void __launch_bounds__(128,4) k_edge_init(
    const float* __restrict__ raw, const int* __restrict__ src,
    const float* __restrict__ W_edge, const float* __restrict__ b_edge,
    const float* __restrict__ W_init, const float* __restrict__ W_me)
{
    extern __shared__ float sm[];
    float* Xs=sm; float* Ws=sm+8320; float* bs=Ws+4352;
    __shared__ float we[64], be[64], rawv[128];
    __shared__ int srcs[128];
    int tid=threadIdx.x, w=tid>>5, lane=tid&31;
    size_t base=(size_t)blockIdx.x*128;
    if (tid<64){ we[tid]=W_edge[tid]; be[tid]=b_edge[tid]; bs[tid]=0.f; }
    rawv[tid]=raw[base+tid]; srcs[tid]=src[base+tid];
    for (int i=tid;i<4096;i+=128) Ws[(i>>6)*68+(i&63)]=W_init[4096+i];
    __syncthreads();
    for (int i=tid;i<8192;i+=128){ int e=i>>6,f=i&63; Xs[e*65+f]=fmaxf(fmaf(rawv[e],we[f],be[f]),0.f); }
    __syncthreads();
    u64 acc[4][8];
    gemm_core<4>(Xs,Ws,bs,w,lane,acc);
    __syncthreads();
    acc_to_os<4>(Xs,w,lane,acc);
    __syncthreads();
    for (int i=tid;i<8192;i+=128){
        int e=i>>6, f=i&63;
        float v=Xs[e*65+f] + __ldg(&g_node_pre[(size_t)srcs[e]*64+f]);
        g_message[base*64+i]=fmaxf(v,0.f);
    }
    __syncthreads();
    for (int i=tid;i<4096;i+=128) Ws[(i>>6)*68+(i&63)]=W_me[4096+i];
    __syncthreads();
    for (int i=tid;i<8192;i+=128){ int e=i>>6,f=i&63; Xs[e*65+f]=fmaxf(fmaf(rawv[e],we[f],be[f]),0.f); }
    __syncthreads();
    gemm_core<4>(Xs,Ws,bs,w,lane,acc);
    __syncthreads();
    acc_to_os<4>(Xs,w,lane,acc);
    __syncthreads();
    for (int i=tid;i<8192;i+=128) g_contrib[base*64+i]=Xs[(i>>6)*65+(i&63)];
}

// ---------------- m = relu(message @ W_me[0:64] + contrib + b_me) ----------------
__global__ void __launch_bounds__(128,4) k_me(const float* __restrict__ W, const float* __restrict__ b)
{
    extern __shared__ float sm[];
    float* Xs=sm; float* Ws=sm+8320; float* bs=Ws+4352;
    int tid=threadIdx.x, w=tid>>5, lane=tid&31;
    size_t base=(size_t)blockIdx.x*128;
    for (int i=tid;i<4096;i+=128) Ws[(i>>6)*68+(i&63)]=W[i];
    if (tid<64) bs[tid]=b[tid];
    for (int i=tid;i<8192;i+=128) Xs[(i>>6)*65+(i&63)]=g_message[base*64+i];
    __syncthreads();
    u64 acc[4][8];
    gemm_core<4>(Xs,Ws,bs,w,lane,acc);
    __syncthreads();
    acc_to_os<4>(Xs,w,lane,acc);
    __syncthreads();
    for (int i=tid;i<8192;i+=128){
        float v=Xs[(i>>6)*65+(i&63)] + g_contrib[base*64+i];
        g_m[base*64+i]=fmaxf(v,0.f);
    }
}

// ---------------- x = relu((agg[src] - m[rev]) @ W_mp + b_mp) ----------------
__global__ void __launch_bounds__(128,4) k_mp(
    const float* __restrict__ W, const float* __restrict__ b,
    const int* __restrict__ src, const int* __restrict__ rev)
{
    extern __shared__ float sm[];
    float* Xs=sm; float* Ws=sm+8320; float* bs=Ws+4352;
    __shared__ int srcs[128], revs[128];
    int tid=threadIdx.x, w=tid>>5, lane=tid&31;
    size_t base=(size_t)blockIdx.x*128;
    srcs[tid]=src[base+tid]; revs[tid]=rev[base+tid];
    for (int i=tid;i<4096;i+=128) Ws[(i>>6)*68+(i&63)]=W[i];
    if (tid<64) bs[tid]=b[tid];
    __syncthreads();
    for (int i=tid;i<8192;i+=128){
        int e=i>>6, f=i&63;
        Xs[e*65+f] = __ldg(&g_agg[(size_t)srcs[e]*64+f]) - __ldg(&g_m[(size_t)revs[e]*64+f]);
    }
    __syncthreads();
    u64 acc[4][8];
    gemm_core<4>(Xs,Ws,bs,w,lane,acc);
    __syncthreads();
    acc_to_os<4>(Xs,w,lane,acc);
    __syncthreads();
    for (int i=tid;i<8192;i+=128) g_x[base*64+i]=fmaxf(Xs[(i>>6)*65+(i&63)],0.f);
}

// ---------------- fused gates + GRU (persistent, 512 threads, R10-proven epilogue: z via smem) ----------------
// smem: Xs[8320] Hs[8320] Wall[6*4352] Zs[16*512] bsm[256]
__global__ void __launch_bounds__(512,1) k_grufuse(
    const float* __restrict__ Wih, const float* __restrict__ bih,
    const float* __restrict__ Whh, const float* __restrict__ bhh)
{
    extern __shared__ float sm[];
    float* Xs  = sm;
    float* Hs  = sm + 8320;
    float* Wall= sm + 16640;
    float* Zs  = sm + 42752;
    float* bsm = sm + 50944;
    int tid=threadIdx.x, w=tid>>5, lane=tid&31;
    const int c0 = (w&7)*8;
    const int e0 = (w>>3)*64 + lane;   // edges e0, e0+32

    for (int i=tid;i<24576;i+=512){
        int m=i>>12, r=i&4095, c=r>>6, k=r&63;
        const float* Wsrc = (m<3)? Wih : Whh;
        int g = (m<3)? m : (m-3);
        Wall[m*4352 + k*68 + c] = Wsrc[(size_t)(g*64+c)*64 + k];
    }
    if (tid<64){
        bsm[tid]     = bih[tid]     + bhh[tid];       // r
        bsm[64+tid]  = bih[64+tid]  + bhh[64+tid];    // z
        bsm[128+tid] = bih[128+tid];                  // in
        bsm[192+tid] = bhh[128+tid];                  // hn
    }
    __syncthreads();

    for (int t=blockIdx.x; t<GRU_TILES; t+=gridDim.x){
        size_t base=(size_t)t*128;
        for (int i=tid;i<8192;i+=512){
            int e=i>>6, f=i&63;
            Xs[e*65+f]=__ldg(&g_x[base*64+i]);
            Hs[e*65+f]=__ldg(&g_message[base*64+i]);
        }
        __syncthreads();

        u64 acc[2][4];
        float rr[16];
        // pass r
        #pragma unroll
        for (int j=0;j<2;j++)
            #pragma unroll
            for (int q=0;q<4;q++) acc[j][q]=pack2(bsm[c0+2*q],bsm[c0+2*q+1]);
        gemm8x2(Xs, Wall+0*4352, c0, e0, acc);
        gemm8x2(Hs, Wall+3*4352, c0, e0, acc);
        #pragma unroll
        for (int j=0;j<2;j++)
            #pragma unroll
            for (int q=0;q<4;q++){
                float2 v=unpack2(acc[j][q]);
                rr[j*8+2*q]=sigf(v.x); rr[j*8+2*q+1]=sigf(v.y);
            }
        // pass z -> smem (same-thread slots, no race)
        #pragma unroll
        for (int j=0;j<2;j++)
            #pragma unroll
            for (int q=0;q<4;q++) acc[j][q]=pack2(bsm[64+c0+2*q],bsm[64+c0+2*q+1]);
        gemm8x2(Xs, Wall+1*4352, c0, e0, acc);
        gemm8x2(Hs, Wall+4*4352, c0, e0, acc);
        #pragma unroll
        for (int j=0;j<2;j++)
            #pragma unroll
            for (int q=0;q<4;q++){
                float2 v=unpack2(acc[j][q]);
                Zs[(j*8+2*q)*512+tid]  =sigf(v.x);
                Zs[(j*8+2*q+1)*512+tid]=sigf(v.y);
            }
        // pass n (two accumulator sets)
        u64 accI[2][4], accH[2][4];
        #pragma unroll
        for (int j=0;j<2;j++)
            #pragma unroll
            for (int q=0;q<4;q++){
                accI[j][q]=pack2(bsm[128+c0+2*q],bsm[128+c0+2*q+1]);
                accH[j][q]=pack2(bsm[192+c0+2*q],bsm[192+c0+2*q+1]);
            }
        gemm8x2(Xs, Wall+2*4352, c0, e0, accI);
        gemm8x2(Hs, Wall+5*4352, c0, e0, accH);
        // combine GRU into registers — no smem writes yet
        #pragma unroll
        for (int j=0;j<2;j++){
            int e=e0+32*j;
            #pragma unroll
            for (int q=0;q<4;q++){
                float2 iv=unpack2(accI[j][q]);
                float2 hv=unpack2(accH[j][q]);
                int cA=c0+2*q, cB=cA+1;
                float nA=tanhf(iv.x + rr[j*8+2*q]  *hv.x);
                float nB=tanhf(iv.y + rr[j*8+2*q+1]*hv.y);
                float zA=Zs[(j*8+2*q)*512+tid],  zB=Zs[(j*8+2*q+1)*512+tid];
                float hA=Hs[e*65+cA], hB=Hs[e*65+cB];
                accI[j][q]=pack2((1.f-zA)*nA+zA*hA, (1.f-zB)*nB+zB*hB);
            }
        }
        __syncthreads();   // ALL reads of Xs/Hs complete before any write
        #pragma unroll
        for (int j=0;j<2;j++){
            int e=e0+32*j;
            #pragma unroll
            for (int q=0;q<4;q++){
                float2 o=unpack2(accI[j][q]);
                Hs[e*65+c0+2*q]  =o.x;
                Hs[e*65+c0+2*q+1]=o.y;
            }
        }
        __syncthreads();
        for (int i=tid;i<8192;i+=512) g_message[base*64+i]=Hs[(i>>6)*65+(i&63)];
        __syncthreads();
    }
}

// ---------------- nodes_out ----------------
__global__ void __launch_bounds__(256) k_nodes_out(
    int iter, float* __restrict__ outM, float* __restrict__ outD,
    const float* __restrict__ Wagg, const float* __restrict__ bagg,
    const float* __restrict__ Wout)
{
    __shared__ float Wa[4096]; __shared__ float ba[64]; __shared__ float Wo[192];
    int tid=threadIdx.x;
    for (int i=tid;i<4096;i+=256) Wa[i]=Wagg[i];
    if (tid<64) ba[tid]=bagg[tid];
    for (int i=tid;i<192;i+=256) Wo[i]=Wout[i];
    __syncthreads();
    int n=blockIdx.x*256+tid;
    if (n>=NN) return;
    float af[64];
    const float4* ar=(const float4*)&g_agg[(size_t)n*64];
    #pragma unroll
    for (int q=0;q<16;q++){ float4 v=ar[q]; af[4*q]=v.x; af[4*q+1]=v.y; af[4*q+2]=v.z; af[4*q+3]=v.w; }
    u64 acc[32];
    #pragma unroll
    for (int j=0;j<32;j++) acc[j]=pack2(ba[2*j],ba[2*j+1]);
    #pragma unroll 4
    for (int k=0;k<64;k++){
        u64 x2=pack2(af[k],af[k]);
        const ulonglong2* wr=(const ulonglong2*)&Wa[k*64];
        #pragma unroll
        for (int q=0;q<16;q++){ ulonglong2 w=wr[q]; fma2(acc[2*q],x2,w.x); fma2(acc[2*q+1],x2,w.y); }
    }
    float l0=0.f,l1=0.f,l2=0.f;
    #pragma unroll
    for (int j=0;j<32;j++){
        float2 v=unpack2(acc[j]);
        float a0=fmaxf(v.x,0.f), a1=fmaxf(v.y,0.f);
        int k0=2*j, k1=2*j+1;
        l0 += a0*Wo[k0*3+0] + a1*Wo[k1*3+0];
        l1 += a0*Wo[k0*3+1] + a1*Wo[k1*3+1];
        l2 += a0*Wo[k0*3+2] + a1*Wo[k1*3+2];
    }
    l0=fmaxf(l0+g_nf_logit[n*3+0],0.f);
    l1=fmaxf(l1+g_nf_logit[n*3+1],0.f);
    l2=fmaxf(l2+g_nf_logit[n*3+2],0.f);
    float mx=fmaxf(l0,fmaxf(l1,l2));
    float e0=expf(l0-mx), e1=expf(l1-mx), e2=expf(l2-mx);
    float sum=e0+e1+e2, ls=logf(sum);
    size_t ob=(size_t)iter*((size_t)NN*3)+(size_t)n*3;
    outM[ob+0]=l0-mx-ls; outM[ob+1]=l1-mx-ls; outM[ob+2]=l2-mx-ls;
    float p2=e2/sum;
    if (iter>0){
        float d=fabsf(p2-g_prevp[n]);
        atomicMax((int*)&outD[iter-1], __float_as_int(d));
    }
    g_prevp[n]=p2;
}

// ---------------- host ----------------
extern "C" void kernel_launch(void* const* d_in, const int* in_sizes, int n_in,
                              void* d_out, int out_size)
{
    const int*   src  = (const int*)  d_in[0];
    const int*   tgt  = (const int*)  d_in[1];
    const int*   rev  = (const int*)  d_in[2];
    const float* raw  = (const float*)d_in[3];
    const float* prob = (const float*)d_in[4];
    const float* seed = (const float*)d_in[5];
    const float* W_node=(const float*)d_in[6],  *b_node=(const float*)d_in[7];
    const float* W_edge=(const float*)d_in[8],  *b_edge=(const float*)d_in[9];
    const float* W_init=(const float*)d_in[10], *b_init=(const float*)d_in[11];
    const float* W_aggr=(const float*)d_in[12], *b_aggr=(const float*)d_in[13];
    const float* W_out =(const float*)d_in[14], *b_out =(const float*)d_in[15];
    const float* W_me  =(const float*)d_in[16], *b_me  =(const float*)d_in[17];
    const float* W_mp  =(const float*)d_in[18], *b_mp  =(const float*)d_in[19];
    const float* W_ih  =(const float*)d_in[20], *W_hh  =(const float*)d_in[21];
    const float* b_ih  =(const float*)d_in[22], *b_hh  =(const float*)d_in[23];

    float* outM = (float*)d_out;
    float* outD = (float*)d_out + (size_t)5*NN*3;

    cudaFuncSetAttribute(k_edge_init, cudaFuncAttributeMaxDynamicSharedMemorySize, DSM);
    cudaFuncSetAttribute(k_me,        cudaFuncAttributeMaxDynamicSharedMemorySize, DSM);
    cudaFuncSetAttribute(k_mp,        cudaFuncAttributeMaxDynamicSharedMemorySize, DSM);
    cudaFuncSetAttribute(k_grufuse,   cudaFuncAttributeMaxDynamicSharedMemorySize, DSM_GRU);

    void *degPtr=0, *msgPtr=0, *mPtr=0;
    cudaGetSymbolAddress(&degPtr, g_deg);
    cudaGetSymbolAddress(&msgPtr, g_message);
    cudaGetSymbolAddress(&mPtr,   g_m);

    // launch order: #6 = k_edge_init (ncu -s 5 -c 1 captures it)
    cudaMemsetAsync(degPtr, 0, NN*sizeof(int));                                             // 1
    cudaMemsetAsync(outD, 0, 4*sizeof(float));                                              // 2
    k_hist<<<EE/256,256>>>(tgt);                                                            // 3
    k_scan<<<1,1024>>>();                                                                   // 4
    k_node<<<(NN+255)/256,256>>>(prob, seed, W_node, b_node, W_init, b_init, W_out, b_out); // 5
    k_edge_init<<<EE/128,128,DSM>>>(raw, src, W_edge, b_edge, W_init, W_me);                // 6 (captured)
    k_fill<<<EE/256,256>>>(tgt);                                                            // 7

    k_gather<<<NN/4,256>>>((const float*)msgPtr);
    k_nodes_out<<<(NN+255)/256,256>>>(0, outM, outD, W_aggr, b_aggr, W_out);

    for (int l=0; l<4; l++){
        k_me<<<EE/128,128,DSM>>>(W_me, b_me);
        k_gather<<<NN/4,256>>>((const float*)mPtr);
        k_mp<<<EE/128,128,DSM>>>(W_mp, b_mp, src, rev);
        k_grufuse<<<GRU_GRID,512,DSM_GRU>>>(W_ih, b_ih, W_hh, b_hh);
        k_gather<<<NN/4,256>>>((const float*)msgPtr);
        k_nodes_out<<<(NN+255)/256,256>>>(l+1, outM, outD, W_aggr, b_aggr, W_out);
    }
}

// round 14
// speedup vs baseline: 1.1535x; 1.1000x over previous
#include <cuda_runtime.h>

#define NN 50000
#define EE 800000

typedef unsigned long long u64;

// ---------------- f32x2 helpers ----------------
__device__ __forceinline__ void fma2(u64 &c, u64 a, u64 b){
    asm("fma.rn.f32x2 %0, %1, %2, %0;" : "+l"(c) : "l"(a), "l"(b));
}
__device__ __forceinline__ u64 pack2(float x, float y){
    u64 r; asm("mov.b64 %0, {%1, %2};" : "=l"(r) : "f"(x), "f"(y)); return r;
}
__device__ __forceinline__ float2 unpack2(u64 v){
    float2 r; asm("mov.b64 {%0, %1}, %2;" : "=f"(r.x), "=f"(r.y) : "l"(v)); return r;
}
__device__ __forceinline__ float sigf(float x){ return 1.f/(1.f+__expf(-x)); }

// ---------------- scratch ----------------
__device__ float g_node_pre[(size_t)NN*64];
__device__ float g_nf_logit[(size_t)NN*3];
__device__ float g_prevp[NN];
__device__ float g_agg[(size_t)NN*64];
__device__ float g_contrib[(size_t)EE*64];
__device__ float g_message[(size_t)EE*64];
__device__ float g_m[(size_t)EE*64];
__device__ float g_x[(size_t)EE*64];
__device__ int   g_deg[NN];
__device__ int   g_rowptr[NN+1];
__device__ int   g_cursor[NN];
__device__ int   g_eid[EE];

#define DSM 50944            // gemm kernels: Xs 8320 + Ws 4352 + bs 64 floats
#define DSM_GRU 204800       // fused gru: Xs 8320 + Hs 8320 + Wall 26112 + Zs 8192 + bsm 256 floats
#define GRU_GRID 152
#define GRU_TILES 6250       // EE/128

// ---------------- GEMM core (register-lean, R11-proven): TE=128 ----------------
template<int NJ>
__device__ __forceinline__ void gemm_core(const float* Xs, const float* Ws, const float* bs,
                                          int w, int lane, u64 (&acc)[NJ][8])
{
    const int c0 = w*16;
    #pragma unroll
    for (int j=0;j<NJ;j++)
        #pragma unroll
        for (int q=0;q<8;q++) acc[j][q]=pack2(bs[c0+2*q],bs[c0+2*q+1]);
    #pragma unroll 2
    for (int k=0;k<64;k++){
        u64 x2[NJ];
        #pragma unroll
        for (int j=0;j<NJ;j++){
            float xk = Xs[(lane+32*j)*65 + k];
            x2[j] = pack2(xk,xk);
        }
        const ulonglong2* wp=(const ulonglong2*)(Ws + k*68 + c0);
        #pragma unroll
        for (int q=0;q<4;q++){
            ulonglong2 wv = wp[q];
            #pragma unroll
            for (int j=0;j<NJ;j++){
                fma2(acc[j][2*q],   x2[j], wv.x);
                fma2(acc[j][2*q+1], x2[j], wv.y);
            }
        }
    }
}

// ---------------- 8-col x 2-edge GEMM core for fused GRU ----------------
__device__ __forceinline__ void gemm8x2(const float* Xs, const float* Wm, int c0, int e0,
                                        u64 (&acc)[2][4])
{
    #pragma unroll 4
    for (int k=0;k<64;k++){
        u64 x2a, x2b;
        { float xk = Xs[e0*65 + k];       x2a = pack2(xk,xk); }
        { float xk = Xs[(e0+32)*65 + k];  x2b = pack2(xk,xk); }
        const ulonglong2* wp=(const ulonglong2*)(Wm + k*68 + c0);
        #pragma unroll
        for (int q=0;q<2;q++){
            ulonglong2 wv = wp[q];
            fma2(acc[0][2*q],   x2a, wv.x);
            fma2(acc[0][2*q+1], x2a, wv.y);
            fma2(acc[1][2*q],   x2b, wv.x);
            fma2(acc[1][2*q+1], x2b, wv.y);
        }
    }
}

// ---------------- CSR build ----------------
__global__ void __launch_bounds__(256) k_hist(const int* __restrict__ tgt){
    int e=blockIdx.x*256+threadIdx.x;
    atomicAdd(&g_deg[tgt[e]],1);
}
__global__ void __launch_bounds__(1024) k_scan(){
    __shared__ int wsum[32];
    __shared__ int carry_s;
    int t=threadIdx.x, lane=t&31, wid=t>>5;
    if (t==0){ g_rowptr[0]=0; carry_s=0; }
    __syncthreads();
    for (int base=0; base<NN; base+=1024){
        int i=base+t;
        int v=(i<NN)? g_deg[i] : 0;
        int s=v;
        #pragma unroll
        for (int o=1;o<32;o<<=1){ int u=__shfl_up_sync(0xffffffffu,s,o); if(lane>=o) s+=u; }
        if (lane==31) wsum[wid]=s;
        __syncthreads();
        if (wid==0){
            int ws=wsum[lane];
            #pragma unroll
            for (int o=1;o<32;o<<=1){ int u=__shfl_up_sync(0xffffffffu,ws,o); if(lane>=o) ws+=u; }
            wsum[lane]=ws;
        }
        __syncthreads();
        int off=(wid>0)? wsum[wid-1] : 0;
        int inc=s+off+carry_s;
        if (i<NN){ g_rowptr[i+1]=inc; g_cursor[i]=inc-v; }
        __syncthreads();
        if (t==1023) carry_s=inc;
        __syncthreads();
    }
}
__global__ void __launch_bounds__(256) k_fill(const int* __restrict__ tgt){
    int e=blockIdx.x*256+threadIdx.x;
    int p=atomicAdd(&g_cursor[tgt[e]],1);
    g_eid[p]=e;
}

// ---------------- segment sum by gather ----------------
__global__ void __launch_bounds__(256) k_gather(const float* __restrict__ S){
    int node=blockIdx.x*4+(threadIdx.x>>6);
    int f=threadIdx.x&63;
    int s=g_rowptr[node], e=g_rowptr[node+1];
    float a=0.f;
    for (int i=s;i<e;i++){
        int eid=__ldg(&g_eid[i]);
        a += __ldg(&S[(size_t)eid*64+f]);
    }
    g_agg[(size_t)node*64+f]=a;
}

// ---------------- per-node precompute ----------------
__global__ void __launch_bounds__(256) k_node(
    const float* __restrict__ prob, const float* __restrict__ seed,
    const float* __restrict__ W_node, const float* __restrict__ b_node,
    const float* __restrict__ W_init, const float* __restrict__ b_init,
    const float* __restrict__ W_out,  const float* __restrict__ b_out)
{
    __shared__ float Wi[4096];
    __shared__ float Wn0[64], Wn1[64], bn[64], bi[64], Wo[192], bo[3];
    int tid = threadIdx.x;
    for (int i=tid;i<4096;i+=256) Wi[i]=W_init[i];
    if (tid<64){ Wn0[tid]=W_node[tid]; Wn1[tid]=W_node[64+tid]; bn[tid]=b_node[tid]; bi[tid]=b_init[tid]; }
    for (int i=tid;i<192;i+=256) Wo[i]=W_out[192+i];
    if (tid<3) bo[tid]=b_out[tid];
    __syncthreads();
    int n = blockIdx.x*256 + tid;
    if (n >= NN) return;
    float p = prob[n], s = seed[n];
    u64 acc[32];
    #pragma unroll
    for (int j=0;j<32;j++) acc[j]=pack2(bi[2*j],bi[2*j+1]);
    float l0=bo[0], l1=bo[1], l2=bo[2];
    #pragma unroll 4
    for (int k=0;k<64;k++){
        float nf = fmaxf(fmaf(p,Wn0[k],fmaf(s,Wn1[k],bn[k])), 0.f);
        u64 x2 = pack2(nf,nf);
        const ulonglong2* wr = (const ulonglong2*)&Wi[k*64];
        #pragma unroll
        for (int q=0;q<16;q++){ ulonglong2 w=wr[q]; fma2(acc[2*q],x2,w.x); fma2(acc[2*q+1],x2,w.y); }
        l0 = fmaf(nf,Wo[k*3],l0); l1 = fmaf(nf,Wo[k*3+1],l1); l2 = fmaf(nf,Wo[k*3+2],l2);
    }
    float4* outp = (float4*)&g_node_pre[(size_t)n*64];
    #pragma unroll
    for (int q=0;q<16;q++){ float2 a=unpack2(acc[2*q]); float2 b=unpack2(acc[2*q+1]); outp[q]=make_float4(a.x,a.y,b.x,b.y); }
    g_nf_logit[n*3]=l0; g_nf_logit[n*3+1]=l1; g_nf_logit[n*3+2]=l2;
}

// ---------------- edge init (TE=128, NJ=4, 4 blocks/SM, direct-store epilogues, Xs reused) ----------------
__global__ void __launch_bounds__(128,4) k_edge_init(
    const float* __restrict__ raw, const int* __restrict__ src,
    const float* __restrict__ W_edge, const float* __restrict__ b_edge,
    const float* __restrict__ W_init, const float* __restrict__ W_me)
{
    extern __shared__ float sm[];
    float* Xs=sm; float* Ws=sm+8320; float* bs=Ws+4352;
    __shared__ float we[64], be[64], rawv[128];
    __shared__ int srcs[128];
    int tid=threadIdx.x, w=tid>>5, lane=tid&31;
    size_t base=(size_t)blockIdx.x*128;
    const int c0=w*16;
    if (tid<64){ we[tid]=W_edge[tid]; be[tid]=b_edge[tid]; bs[tid]=0.f; }
    rawv[tid]=raw[base+tid]; srcs[tid]=src[base+tid];
    for (int i=tid;i<4096;i+=128) Ws[(i>>6)*68+(i&63)]=W_init[4096+i];
    __syncthreads();
    for (int i=tid;i<8192;i+=128){ int e=i>>6,f=i&63; Xs[e*65+f]=fmaxf(fmaf(rawv[e],we[f],be[f]),0.f); }
    __syncthreads();
    u64 acc[4][8];
    gemm_core<4>(Xs,Ws,bs,w,lane,acc);
    // epilogue 1: message = relu(acc + node_pre[src]) direct
    #pragma unroll
    for (int j=0;j<4;j++){
        int e=lane+32*j;
        size_t erow=(base+e)*64 + c0;
        const float4* np=(const float4*)&g_node_pre[(size_t)srcs[e]*64 + c0];
        float4* out=(float4*)&g_message[erow];
        #pragma unroll
        for (int q=0;q<4;q++){
            float2 a=unpack2(acc[j][2*q]), b=unpack2(acc[j][2*q+1]);
            float4 nv=np[q];
            out[q]=make_float4(fmaxf(a.x+nv.x,0.f),fmaxf(a.y+nv.y,0.f),
                               fmaxf(b.x+nv.z,0.f),fmaxf(b.y+nv.w,0.f));
        }
    }
    __syncthreads();   // all gemm reads of Ws done before reload
    for (int i=tid;i<4096;i+=128) Ws[(i>>6)*68+(i&63)]=W_me[4096+i];
    __syncthreads();
    gemm_core<4>(Xs,Ws,bs,w,lane,acc);   // Xs (edge_feat) intact
    // epilogue 2: contrib raw
    #pragma unroll
    for (int j=0;j<4;j++){
        size_t erow=(base+lane+32*j)*64 + c0;
        float4* out=(float4*)&g_contrib[erow];
        #pragma unroll
        for (int q=0;q<4;q++){
            float2 a=unpack2(acc[j][2*q]), b=unpack2(acc[j][2*q+1]);
            out[q]=make_float4(a.x,a.y,b.x,b.y);
        }
    }
}

// ---------------- m = relu(message @ W_me[0:64] + contrib + b_me), direct store ----------------
__global__ void __launch_bounds__(128,4) k_me(const float* __restrict__ W, const float* __restrict__ b)
{
    extern __shared__ float sm[];
    float* Xs=sm; float* Ws=sm+8320; float* bs=Ws+4352;
    int tid=threadIdx.x, w=tid>>5, lane=tid&31;
    size_t base=(size_t)blockIdx.x*128;
    const int c0=w*16;
    for (int i=tid;i<4096;i+=128) Ws[(i>>6)*68+(i&63)]=W[i];
    if (tid<64) bs[tid]=b[tid];
    for (int i=tid;i<8192;i+=128) Xs[(i>>6)*65+(i&63)]=g_message[base*64+i];
    __syncthreads();
    u64 acc[4][8];
    gemm_core<4>(Xs,Ws,bs,w,lane,acc);
    #pragma unroll
    for (int j=0;j<4;j++){
        size_t erow=(base+lane+32*j)*64 + c0;
        const float4* ct=(const float4*)&g_contrib[erow];
        float4* out=(float4*)&g_m[erow];
        #pragma unroll
        for (int q=0;q<4;q++){
            float2 a=unpack2(acc[j][2*q]), b2=unpack2(acc[j][2*q+1]);
            float4 c=ct[q];
            out[q]=make_float4(fmaxf(a.x+c.x,0.f),fmaxf(a.y+c.y,0.f),
                               fmaxf(b2.x+c.z,0.f),fmaxf(b2.y+c.w,0.f));
        }
    }
}

// ---------------- x = relu((agg[src] - m[rev]) @ W_mp + b_mp), direct store ----------------
__global__ void __launch_bounds__(128,4) k_mp(
    const float* __restrict__ W, const float* __restrict__ b,
    const int* __restrict__ src, const int* __restrict__ rev)
{
    extern __shared__ float sm[];
    float* Xs=sm; float* Ws=sm+8320; float* bs=Ws+4352;
    __shared__ int srcs[128], revs[128];
    int tid=threadIdx.x, w=tid>>5, lane=tid&31;
    size_t base=(size_t)blockIdx.x*128;
    const int c0=w*16;
    srcs[tid]=src[base+tid]; revs[tid]=rev[base+tid];
    for (int i=tid;i<4096;i+=128) Ws[(i>>6)*68+(i&63)]=W[i];
    if (tid<64) bs[tid]=b[tid];
    __syncthreads();
    for (int i=tid;i<8192;i+=128){
        int e=i>>6, f=i&63;
        Xs[e*65+f] = __ldg(&g_agg[(size_t)srcs[e]*64+f]) - __ldg(&g_m[(size_t)revs[e]*64+f]);
    }
    __syncthreads();
    u64 acc[4][8];
    gemm_core<4>(Xs,Ws,bs,w,lane,acc);
    #pragma unroll
    for (int j=0;j<4;j++){
        size_t erow=(base+lane+32*j)*64 + c0;
        float4* out=(float4*)&g_x[erow];
        #pragma unroll
        for (int q=0;q<4;q++){
            float2 a=unpack2(acc[j][2*q]), b2=unpack2(acc[j][2*q+1]);
            out[q]=make_float4(fmaxf(a.x,0.f),fmaxf(a.y,0.f),fmaxf(b2.x,0.f),fmaxf(b2.y,0.f));
        }
    }
}

// ---------------- fused gates + GRU (persistent, 512 threads, z via smem, direct gmem output) ----------------
// smem: Xs[8320] Hs[8320] Wall[6*4352] Zs[16*512] bsm[256]
__global__ void __launch_bounds__(512,1) k_grufuse(
    const float* __restrict__ Wih, const float* __restrict__ bih,
    const float* __restrict__ Whh, const float* __restrict__ bhh)
{
    extern __shared__ float sm[];
    float* Xs  = sm;
    float* Hs  = sm + 8320;
    float* Wall= sm + 16640;
    float* Zs  = sm + 42752;
    float* bsm = sm + 50944;
    int tid=threadIdx.x, w=tid>>5, lane=tid&31;
    const int c0 = (w&7)*8;
    const int e0 = (w>>3)*64 + lane;   // edges e0, e0+32

    for (int i=tid;i<24576;i+=512){
        int m=i>>12, r=i&4095, c=r>>6, k=r&63;
        const float* Wsrc = (m<3)? Wih : Whh;
        int g = (m<3)? m : (m-3);
        Wall[m*4352 + k*68 + c] = Wsrc[(size_t)(g*64+c)*64 + k];
    }
    if (tid<64){
        bsm[tid]     = bih[tid]     + bhh[tid];       // r
        bsm[64+tid]  = bih[64+tid]  + bhh[64+tid];    // z
        bsm[128+tid] = bih[128+tid];                  // in
        bsm[192+tid] = bhh[128+tid];                  // hn
    }
    __syncthreads();

    for (int t=blockIdx.x; t<GRU_TILES; t+=gridDim.x){
        size_t base=(size_t)t*128;
        for (int i=tid;i<8192;i+=512){
            int e=i>>6, f=i&63;
            Xs[e*65+f]=__ldg(&g_x[base*64+i]);
            Hs[e*65+f]=__ldg(&g_message[base*64+i]);
        }
        __syncthreads();

        u64 acc[2][4];
        float rr[16];
        // pass r
        #pragma unroll
        for (int j=0;j<2;j++)
            #pragma unroll
            for (int q=0;q<4;q++) acc[j][q]=pack2(bsm[c0+2*q],bsm[c0+2*q+1]);
        gemm8x2(Xs, Wall+0*4352, c0, e0, acc);
        gemm8x2(Hs, Wall+3*4352, c0, e0, acc);
        #pragma unroll
        for (int j=0;j<2;j++)
            #pragma unroll
            for (int q=0;q<4;q++){
                float2 v=unpack2(acc[j][q]);
                rr[j*8+2*q]=sigf(v.x); rr[j*8+2*q+1]=sigf(v.y);
            }
        // pass z -> smem (same-thread slots, no race)
        #pragma unroll
        for (int j=0;j<2;j++)
            #pragma unroll
            for (int q=0;q<4;q++) acc[j][q]=pack2(bsm[64+c0+2*q],bsm[64+c0+2*q+1]);
        gemm8x2(Xs, Wall+1*4352, c0, e0, acc);
        gemm8x2(Hs, Wall+4*4352, c0, e0, acc);
        #pragma unroll
        for (int j=0;j<2;j++)
            #pragma unroll
            for (int q=0;q<4;q++){
                float2 v=unpack2(acc[j][q]);
                Zs[(j*8+2*q)*512+tid]  =sigf(v.x);
                Zs[(j*8+2*q+1)*512+tid]=sigf(v.y);
            }
        // pass n (two accumulator sets)
        u64 accI[2][4], accH[2][4];
        #pragma unroll
        for (int j=0;j<2;j++)
            #pragma unroll
            for (int q=0;q<4;q++){
                accI[j][q]=pack2(bsm[128+c0+2*q],bsm[128+c0+2*q+1]);
                accH[j][q]=pack2(bsm[192+c0+2*q],bsm[192+c0+2*q+1]);
            }
        gemm8x2(Xs, Wall+2*4352, c0, e0, accI);
        gemm8x2(Hs, Wall+5*4352, c0, e0, accH);
        // combine + DIRECT gmem store (Hs never modified -> no pre-store barrier)
        #pragma unroll
        for (int j=0;j<2;j++){
            int e=e0+32*j;
            size_t erow=(base+e)*64 + c0;
            float4 o0, o1;
            {
                float2 iv=unpack2(accI[j][0]); float2 hv=unpack2(accH[j][0]);
                float nA=tanhf(iv.x + rr[j*8+0]*hv.x);
                float nB=tanhf(iv.y + rr[j*8+1]*hv.y);
                float zA=Zs[(j*8+0)*512+tid], zB=Zs[(j*8+1)*512+tid];
                o0.x=(1.f-zA)*nA+zA*Hs[e*65+c0+0];
                o0.y=(1.f-zB)*nB+zB*Hs[e*65+c0+1];
            }{
                float2 iv=unpack2(accI[j][1]); float2 hv=unpack2(accH[j][1]);
                float nA=tanhf(iv.x + rr[j*8+2]*hv.x);
                float nB=tanhf(iv.y + rr[j*8+3]*hv.y);
                float zA=Zs[(j*8+2)*512+tid], zB=Zs[(j*8+3)*512+tid];
                o0.z=(1.f-zA)*nA+zA*Hs[e*65+c0+2];
                o0.w=(1.f-zB)*nB+zB*Hs[e*65+c0+3];
            }{
                float2 iv=unpack2(accI[j][2]); float2 hv=unpack2(accH[j][2]);
                float nA=tanhf(iv.x + rr[j*8+4]*hv.x);
                float nB=tanhf(iv.y + rr[j*8+5]*hv.y);
                float zA=Zs[(j*8+4)*512+tid], zB=Zs[(j*8+5)*512+tid];
                o1.x=(1.f-zA)*nA+zA*Hs[e*65+c0+4];
                o1.y=(1.f-zB)*nB+zB*Hs[e*65+c0+5];
            }{
                float2 iv=unpack2(accI[j][3]); float2 hv=unpack2(accH[j][3]);
                float nA=tanhf(iv.x + rr[j*8+6]*hv.x);
                float nB=tanhf(iv.y + rr[j*8+7]*hv.y);
                float zA=Zs[(j*8+6)*512+tid], zB=Zs[(j*8+7)*512+tid];
                o1.z=(1.f-zA)*nA+zA*Hs[e*65+c0+6];
                o1.w=(1.f-zB)*nB+zB*Hs[e*65+c0+7];
            }
            float4* out=(float4*)&g_message[erow];
            out[0]=o0; out[1]=o1;
        }
        __syncthreads();   // all reads of Xs/Hs done before next tile's staging
    }
}

// ---------------- nodes_out ----------------
__global__ void __launch_bounds__(256) k_nodes_out(
    int iter, float* __restrict__ outM, float* __restrict__ outD,
    const float* __restrict__ Wagg, const float* __restrict__ bagg,
    const float* __restrict__ Wout)
{
    __shared__ float Wa[4096]; __shared__ float ba[64]; __shared__ float Wo[192];
    int tid=threadIdx.x;
    for (int i=tid;i<4096;i+=256) Wa[i]=Wagg[i];
    if (tid<64) ba[tid]=bagg[tid];
    for (int i=tid;i<192;i+=256) Wo[i]=Wout[i];
    __syncthreads();
    int n=blockIdx.x*256+tid;
    if (n>=NN) return;
    float af[64];
    const float4* ar=(const float4*)&g_agg[(size_t)n*64];
    #pragma unroll
    for (int q=0;q<16;q++){ float4 v=ar[q]; af[4*q]=v.x; af[4*q+1]=v.y; af[4*q+2]=v.z; af[4*q+3]=v.w; }
    u64 acc[32];
    #pragma unroll
    for (int j=0;j<32;j++) acc[j]=pack2(ba[2*j],ba[2*j+1]);
    #pragma unroll 4
    for (int k=0;k<64;k++){
        u64 x2=pack2(af[k],af[k]);
        const ulonglong2* wr=(const ulonglong2*)&Wa[k*64];
        #pragma unroll
        for (int q=0;q<16;q++){ ulonglong2 w=wr[q]; fma2(acc[2*q],x2,w.x); fma2(acc[2*q+1],x2,w.y); }
    }
    float l0=0.f,l1=0.f,l2=0.f;
    #pragma unroll
    for (int j=0;j<32;j++){
        float2 v=unpack2(acc[j]);
        float a0=fmaxf(v.x,0.f), a1=fmaxf(v.y,0.f);
        int k0=2*j, k1=2*j+1;
        l0 += a0*Wo[k0*3+0] + a1*Wo[k1*3+0];
        l1 += a0*Wo[k0*3+1] + a1*Wo[k1*3+1];
        l2 += a0*Wo[k0*3+2] + a1*Wo[k1*3+2];
    }
    l0=fmaxf(l0+g_nf_logit[n*3+0],0.f);
    l1=fmaxf(l1+g_nf_logit[n*3+1],0.f);
    l2=fmaxf(l2+g_nf_logit[n*3+2],0.f);
    float mx=fmaxf(l0,fmaxf(l1,l2));
    float e0=expf(l0-mx), e1=expf(l1-mx), e2=expf(l2-mx);
    float sum=e0+e1+e2, ls=logf(sum);
    size_t ob=(size_t)iter*((size_t)NN*3)+(size_t)n*3;
    outM[ob+0]=l0-mx-ls; outM[ob+1]=l1-mx-ls; outM[ob+2]=l2-mx-ls;
    float p2=e2/sum;
    if (iter>0){
        float d=fabsf(p2-g_prevp[n]);
        atomicMax((int*)&outD[iter-1], __float_as_int(d));
    }
    g_prevp[n]=p2;
}

// ---------------- host ----------------
extern "C" void kernel_launch(void* const* d_in, const int* in_sizes, int n_in,
                              void* d_out, int out_size)
{
    const int*   src  = (const int*)  d_in[0];
    const int*   tgt  = (const int*)  d_in[1];
    const int*   rev  = (const int*)  d_in[2];
    const float* raw  = (const float*)d_in[3];
    const float* prob = (const float*)d_in[4];
    const float* seed = (const float*)d_in[5];
    const float* W_node=(const float*)d_in[6],  *b_node=(const float*)d_in[7];
    const float* W_edge=(const float*)d_in[8],  *b_edge=(const float*)d_in[9];
    const float* W_init=(const float*)d_in[10], *b_init=(const float*)d_in[11];
    const float* W_aggr=(const float*)d_in[12], *b_aggr=(const float*)d_in[13];
    const float* W_out =(const float*)d_in[14], *b_out =(const float*)d_in[15];
    const float* W_me  =(const float*)d_in[16], *b_me  =(const float*)d_in[17];
    const float* W_mp  =(const float*)d_in[18], *b_mp  =(const float*)d_in[19];
    const float* W_ih  =(const float*)d_in[20], *W_hh  =(const float*)d_in[21];
    const float* b_ih  =(const float*)d_in[22], *b_hh  =(const float*)d_in[23];

    float* outM = (float*)d_out;
    float* outD = (float*)d_out + (size_t)5*NN*3;

    cudaFuncSetAttribute(k_edge_init, cudaFuncAttributeMaxDynamicSharedMemorySize, DSM);
    cudaFuncSetAttribute(k_me,        cudaFuncAttributeMaxDynamicSharedMemorySize, DSM);
    cudaFuncSetAttribute(k_mp,        cudaFuncAttributeMaxDynamicSharedMemorySize, DSM);
    cudaFuncSetAttribute(k_grufuse,   cudaFuncAttributeMaxDynamicSharedMemorySize, DSM_GRU);

    void *degPtr=0, *msgPtr=0, *mPtr=0;
    cudaGetSymbolAddress(&degPtr, g_deg);
    cudaGetSymbolAddress(&msgPtr, g_message);
    cudaGetSymbolAddress(&mPtr,   g_m);

    // launch order: #6 = k_edge_init (ncu -s 5 -c 1 captures it)
    cudaMemsetAsync(degPtr, 0, NN*sizeof(int));                                             // 1
    cudaMemsetAsync(outD, 0, 4*sizeof(float));                                              // 2
    k_hist<<<EE/256,256>>>(tgt);                                                            // 3
    k_scan<<<1,1024>>>();                                                                   // 4
    k_node<<<(NN+255)/256,256>>>(prob, seed, W_node, b_node, W_init, b_init, W_out, b_out); // 5
    k_edge_init<<<EE/128,128,DSM>>>(raw, src, W_edge, b_edge, W_init, W_me);                // 6 (captured)
    k_fill<<<EE/256,256>>>(tgt);                                                            // 7

    k_gather<<<NN/4,256>>>((const float*)msgPtr);
    k_nodes_out<<<(NN+255)/256,256>>>(0, outM, outD, W_aggr, b_aggr, W_out);

    for (int l=0; l<4; l++){
        k_me<<<EE/128,128,DSM>>>(W_me, b_me);
        k_gather<<<NN/4,256>>>((const float*)mPtr);
        k_mp<<<EE/128,128,DSM>>>(W_mp, b_mp, src, rev);
        k_grufuse<<<GRU_GRID,512,DSM_GRU>>>(W_ih, b_ih, W_hh, b_hh);
        k_gather<<<NN/4,256>>>((const float*)msgPtr);
        k_nodes_out<<<(NN+255)/256,256>>>(l+1, outM, outD, W_aggr, b_aggr, W_out);
    }
}

// round 15
// speedup vs baseline: 1.1774x; 1.0207x over previous
#include <cuda_runtime.h>

#define NN 50000
#define EE 800000

typedef unsigned long long u64;

// ---------------- f32x2 helpers ----------------
__device__ __forceinline__ void fma2(u64 &c, u64 a, u64 b){
    asm("fma.rn.f32x2 %0, %1, %2, %0;" : "+l"(c) : "l"(a), "l"(b));
}
__device__ __forceinline__ u64 pack2(float x, float y){
    u64 r; asm("mov.b64 %0, {%1, %2};" : "=l"(r) : "f"(x), "f"(y)); return r;
}
__device__ __forceinline__ float2 unpack2(u64 v){
    float2 r; asm("mov.b64 {%0, %1}, %2;" : "=f"(r.x), "=f"(r.y) : "l"(v)); return r;
}
__device__ __forceinline__ float sigf(float x){ return 1.f/(1.f+__expf(-x)); }

// ---------------- scratch ----------------
__device__ float g_node_pre[(size_t)NN*64];
__device__ float g_nf_logit[(size_t)NN*3];
__device__ float g_prevp[NN];
__device__ float g_agg[(size_t)NN*64];
__device__ float g_contrib[(size_t)EE*64];
__device__ float g_message[(size_t)EE*64];
__device__ float g_m[(size_t)EE*64];
__device__ float g_x[(size_t)EE*64];
__device__ int   g_deg[NN];
__device__ int   g_rowptr[NN+1];
__device__ int   g_cursor[NN];
__device__ int   g_eid[EE];

#define DSM 50944            // gemm kernels: Xs 8320 + Ws 4352 + bs 64 floats
#define DSM_GRU 204800       // fused gru: Xs 8320 + Hs 8320 + Wall 26112 + Zs 8192 + bsm 256 floats
#define GRU_GRID 152
#define GRU_TILES 6250       // EE/128

// ---------------- GEMM core (register-lean, R11-proven): TE=128 ----------------
template<int NJ>
__device__ __forceinline__ void gemm_core(const float* Xs, const float* Ws, const float* bs,
                                          int w, int lane, u64 (&acc)[NJ][8])
{
    const int c0 = w*16;
    #pragma unroll
    for (int j=0;j<NJ;j++)
        #pragma unroll
        for (int q=0;q<8;q++) acc[j][q]=pack2(bs[c0+2*q],bs[c0+2*q+1]);
    #pragma unroll 2
    for (int k=0;k<64;k++){
        u64 x2[NJ];
        #pragma unroll
        for (int j=0;j<NJ;j++){
            float xk = Xs[(lane+32*j)*65 + k];
            x2[j] = pack2(xk,xk);
        }
        const ulonglong2* wp=(const ulonglong2*)(Ws + k*68 + c0);
        #pragma unroll
        for (int q=0;q<4;q++){
            ulonglong2 wv = wp[q];
            #pragma unroll
            for (int j=0;j<NJ;j++){
                fma2(acc[j][2*q],   x2[j], wv.x);
                fma2(acc[j][2*q+1], x2[j], wv.y);
            }
        }
    }
}

// ---------------- fused rz walk: acc_r += X@Wir + H@Whr ; acc_z += X@Wiz + H@Whz ----------------
__device__ __forceinline__ void gemm_rz(const float* Xs, const float* Hs, const float* Wall,
                                        int c0, int e0, u64 (&ar)[2][4], u64 (&az)[2][4])
{
    const float* Wxr = Wall + 0*4352;
    const float* Wxz = Wall + 1*4352;
    const float* Whr = Wall + 3*4352;
    const float* Whz = Wall + 4*4352;
    #pragma unroll 2
    for (int k=0;k<64;k++){
        u64 xa,xb,ha,hb;
        { float v=Xs[e0*65+k];      xa=pack2(v,v); }
        { float v=Xs[(e0+32)*65+k]; xb=pack2(v,v); }
        { float v=Hs[e0*65+k];      ha=pack2(v,v); }
        { float v=Hs[(e0+32)*65+k]; hb=pack2(v,v); }
        const ulonglong2* pxr=(const ulonglong2*)(Wxr + k*68 + c0);
        const ulonglong2* pxz=(const ulonglong2*)(Wxz + k*68 + c0);
        const ulonglong2* phr=(const ulonglong2*)(Whr + k*68 + c0);
        const ulonglong2* phz=(const ulonglong2*)(Whz + k*68 + c0);
        #pragma unroll
        for (int q=0;q<2;q++){
            ulonglong2 wxr=pxr[q], wxz=pxz[q];
            // X contributions (all independent)
            fma2(ar[0][2*q],xa,wxr.x); fma2(ar[0][2*q+1],xa,wxr.y);
            fma2(ar[1][2*q],xb,wxr.x); fma2(ar[1][2*q+1],xb,wxr.y);
            fma2(az[0][2*q],xa,wxz.x); fma2(az[0][2*q+1],xa,wxz.y);
            fma2(az[1][2*q],xb,wxz.x); fma2(az[1][2*q+1],xb,wxz.y);
            ulonglong2 whr=phr[q], whz=phz[q];
            // H contributions (dep distance >= 8 instrs > 4cyc RAW)
            fma2(ar[0][2*q],ha,whr.x); fma2(ar[0][2*q+1],ha,whr.y);
            fma2(ar[1][2*q],hb,whr.x); fma2(ar[1][2*q+1],hb,whr.y);
            fma2(az[0][2*q],ha,whz.x); fma2(az[0][2*q+1],ha,whz.y);
            fma2(az[1][2*q],hb,whz.x); fma2(az[1][2*q+1],hb,whz.y);
        }
    }
}

// ---------------- fused n walk: ai += X@Win ; ah += H@Whn ----------------
__device__ __forceinline__ void gemm_n(const float* Xs, const float* Hs, const float* Wall,
                                       int c0, int e0, u64 (&ai)[2][4], u64 (&ah)[2][4])
{
    const float* Wxn = Wall + 2*4352;
    const float* Whn = Wall + 5*4352;
    #pragma unroll 2
    for (int k=0;k<64;k++){
        u64 xa,xb,ha,hb;
        { float v=Xs[e0*65+k];      xa=pack2(v,v); }
        { float v=Xs[(e0+32)*65+k]; xb=pack2(v,v); }
        { float v=Hs[e0*65+k];      ha=pack2(v,v); }
        { float v=Hs[(e0+32)*65+k]; hb=pack2(v,v); }
        const ulonglong2* pxn=(const ulonglong2*)(Wxn + k*68 + c0);
        const ulonglong2* phn=(const ulonglong2*)(Whn + k*68 + c0);
        #pragma unroll
        for (int q=0;q<2;q++){
            ulonglong2 wxn=pxn[q], whn=phn[q];
            fma2(ai[0][2*q],xa,wxn.x); fma2(ai[0][2*q+1],xa,wxn.y);
            fma2(ai[1][2*q],xb,wxn.x); fma2(ai[1][2*q+1],xb,wxn.y);
            fma2(ah[0][2*q],ha,whn.x); fma2(ah[0][2*q+1],ha,whn.y);
            fma2(ah[1][2*q],hb,whn.x); fma2(ah[1][2*q+1],hb,whn.y);
        }
    }
}

// ---------------- CSR build ----------------
__global__ void __launch_bounds__(256) k_hist(const int* __restrict__ tgt){
    int e=blockIdx.x*256+threadIdx.x;
    atomicAdd(&g_deg[tgt[e]],1);
}
__global__ void __launch_bounds__(1024) k_scan(){
    __shared__ int wsum[32];
    __shared__ int carry_s;
    int t=threadIdx.x, lane=t&31, wid=t>>5;
    if (t==0){ g_rowptr[0]=0; carry_s=0; }
    __syncthreads();
    for (int base=0; base<NN; base+=1024){
        int i=base+t;
        int v=(i<NN)? g_deg[i] : 0;
        int s=v;
        #pragma unroll
        for (int o=1;o<32;o<<=1){ int u=__shfl_up_sync(0xffffffffu,s,o); if(lane>=o) s+=u; }
        if (lane==31) wsum[wid]=s;
        __syncthreads();
        if (wid==0){
            int ws=wsum[lane];
            #pragma unroll
            for (int o=1;o<32;o<<=1){ int u=__shfl_up_sync(0xffffffffu,ws,o); if(lane>=o) ws+=u; }
            wsum[lane]=ws;
        }
        __syncthreads();
        int off=(wid>0)? wsum[wid-1] : 0;
        int inc=s+off+carry_s;
        if (i<NN){ g_rowptr[i+1]=inc; g_cursor[i]=inc-v; }
        __syncthreads();
        if (t==1023) carry_s=inc;
        __syncthreads();
    }
}
__global__ void __launch_bounds__(256) k_fill(const int* __restrict__ tgt){
    int e=blockIdx.x*256+threadIdx.x;
    int p=atomicAdd(&g_cursor[tgt[e]],1);
    g_eid[p]=e;
}

// ---------------- segment sum by gather ----------------
__global__ void __launch_bounds__(256) k_gather(const float* __restrict__ S){
    int node=blockIdx.x*4+(threadIdx.x>>6);
    int f=threadIdx.x&63;
    int s=g_rowptr[node], e=g_rowptr[node+1];
    float a=0.f;
    for (int i=s;i<e;i++){
        int eid=__ldg(&g_eid[i]);
        a += __ldg(&S[(size_t)eid*64+f]);
    }
    g_agg[(size_t)node*64+f]=a;
}

// ---------------- per-node precompute ----------------
__global__ void __launch_bounds__(256) k_node(
    const float* __restrict__ prob, const float* __restrict__ seed,
    const float* __restrict__ W_node, const float* __restrict__ b_node,
    const float* __restrict__ W_init, const float* __restrict__ b_init,
    const float* __restrict__ W_out,  const float* __restrict__ b_out)
{
    __shared__ float Wi[4096];
    __shared__ float Wn0[64], Wn1[64], bn[64], bi[64], Wo[192], bo[3];
    int tid = threadIdx.x;
    for (int i=tid;i<4096;i+=256) Wi[i]=W_init[i];
    if (tid<64){ Wn0[tid]=W_node[tid]; Wn1[tid]=W_node[64+tid]; bn[tid]=b_node[tid]; bi[tid]=b_init[tid]; }
    for (int i=tid;i<192;i+=256) Wo[i]=W_out[192+i];
    if (tid<3) bo[tid]=b_out[tid];
    __syncthreads();
    int n = blockIdx.x*256 + tid;
    if (n >= NN) return;
    float p = prob[n], s = seed[n];
    u64 acc[32];
    #pragma unroll
    for (int j=0;j<32;j++) acc[j]=pack2(bi[2*j],bi[2*j+1]);
    float l0=bo[0], l1=bo[1], l2=bo[2];
    #pragma unroll 4
    for (int k=0;k<64;k++){
        float nf = fmaxf(fmaf(p,Wn0[k],fmaf(s,Wn1[k],bn[k])), 0.f);
        u64 x2 = pack2(nf,nf);
        const ulonglong2* wr = (const ulonglong2*)&Wi[k*64];
        #pragma unroll
        for (int q=0;q<16;q++){ ulonglong2 w=wr[q]; fma2(acc[2*q],x2,w.x); fma2(acc[2*q+1],x2,w.y); }
        l0 = fmaf(nf,Wo[k*3],l0); l1 = fmaf(nf,Wo[k*3+1],l1); l2 = fmaf(nf,Wo[k*3+2],l2);
    }
    float4* outp = (float4*)&g_node_pre[(size_t)n*64];
    #pragma unroll
    for (int q=0;q<16;q++){ float2 a=unpack2(acc[2*q]); float2 b=unpack2(acc[2*q+1]); outp[q]=make_float4(a.x,a.y,b.x,b.y); }
    g_nf_logit[n*3]=l0; g_nf_logit[n*3+1]=l1; g_nf_logit[n*3+2]=l2;
}

// ---------------- edge init (TE=128, NJ=4, 4 blocks/SM, direct-store epilogues, Xs reused) ----------------
__global__ void __launch_bounds__(128,4) k_edge_init(
    const float* __restrict__ raw, const int* __restrict__ src,
    const float* __restrict__ W_edge, const float* __restrict__ b_edge,
    const float* __restrict__ W_init, const float* __restrict__ W_me)
{
    extern __shared__ float sm[];
    float* Xs=sm; float* Ws=sm+8320; float* bs=Ws+4352;
    __shared__ float we[64], be[64], rawv[128];
    __shared__ int srcs[128];
    int tid=threadIdx.x, w=tid>>5, lane=tid&31;
    size_t base=(size_t)blockIdx.x*128;
    const int c0=w*16;
    if (tid<64){ we[tid]=W_edge[tid]; be[tid]=b_edge[tid]; bs[tid]=0.f; }
    rawv[tid]=raw[base+tid]; srcs[tid]=src[base+tid];
    for (int i=tid;i<4096;i+=128) Ws[(i>>6)*68+(i&63)]=W_init[4096+i];
    __syncthreads();
    for (int i=tid;i<8192;i+=128){ int e=i>>6,f=i&63; Xs[e*65+f]=fmaxf(fmaf(rawv[e],we[f],be[f]),0.f); }
    __syncthreads();
    u64 acc[4][8];
    gemm_core<4>(Xs,Ws,bs,w,lane,acc);
    #pragma unroll
    for (int j=0;j<4;j++){
        int e=lane+32*j;
        size_t erow=(base+e)*64 + c0;
        const float4* np=(const float4*)&g_node_pre[(size_t)srcs[e]*64 + c0];
        float4* out=(float4*)&g_message[erow];
        #pragma unroll
        for (int q=0;q<4;q++){
            float2 a=unpack2(acc[j][2*q]), b=unpack2(acc[j][2*q+1]);
            float4 nv=np[q];
            out[q]=make_float4(fmaxf(a.x+nv.x,0.f),fmaxf(a.y+nv.y,0.f),
                               fmaxf(b.x+nv.z,0.f),fmaxf(b.y+nv.w,0.f));
        }
    }
    __syncthreads();
    for (int i=tid;i<4096;i+=128) Ws[(i>>6)*68+(i&63)]=W_me[4096+i];
    __syncthreads();
    gemm_core<4>(Xs,Ws,bs,w,lane,acc);
    #pragma unroll
    for (int j=0;j<4;j++){
        size_t erow=(base+lane+32*j)*64 + c0;
        float4* out=(float4*)&g_contrib[erow];
        #pragma unroll
        for (int q=0;q<4;q++){
            float2 a=unpack2(acc[j][2*q]), b=unpack2(acc[j][2*q+1]);
            out[q]=make_float4(a.x,a.y,b.x,b.y);
        }
    }
}

// ---------------- m = relu(message @ W_me[0:64] + contrib + b_me), direct store ----------------
__global__ void __launch_bounds__(128,4) k_me(const float* __restrict__ W, const float* __restrict__ b)
{
    extern __shared__ float sm[];
    float* Xs=sm; float* Ws=sm+8320; float* bs=Ws+4352;
    int tid=threadIdx.x, w=tid>>5, lane=tid&31;
    size_t base=(size_t)blockIdx.x*128;
    const int c0=w*16;
    for (int i=tid;i<4096;i+=128) Ws[(i>>6)*68+(i&63)]=W[i];
    if (tid<64) bs[tid]=b[tid];
    for (int i=tid;i<8192;i+=128) Xs[(i>>6)*65+(i&63)]=g_message[base*64+i];
    __syncthreads();
    u64 acc[4][8];
    gemm_core<4>(Xs,Ws,bs,w,lane,acc);
    #pragma unroll
    for (int j=0;j<4;j++){
        size_t erow=(base+lane+32*j)*64 + c0;
        const float4* ct=(const float4*)&g_contrib[erow];
        float4* out=(float4*)&g_m[erow];
        #pragma unroll
        for (int q=0;q<4;q++){
            float2 a=unpack2(acc[j][2*q]), b2=unpack2(acc[j][2*q+1]);
            float4 c=ct[q];
            out[q]=make_float4(fmaxf(a.x+c.x,0.f),fmaxf(a.y+c.y,0.f),
                               fmaxf(b2.x+c.z,0.f),fmaxf(b2.y+c.w,0.f));
        }
    }
}

// ---------------- x = relu((agg[src] - m[rev]) @ W_mp + b_mp), direct store ----------------
__global__ void __launch_bounds__(128,4) k_mp(
    const float* __restrict__ W, const float* __restrict__ b,
    const int* __restrict__ src, const int* __restrict__ rev)
{
    extern __shared__ float sm[];
    float* Xs=sm; float* Ws=sm+8320; float* bs=Ws+4352;
    __shared__ int srcs[128], revs[128];
    int tid=threadIdx.x, w=tid>>5, lane=tid&31;
    size_t base=(size_t)blockIdx.x*128;
    const int c0=w*16;
    srcs[tid]=src[base+tid]; revs[tid]=rev[base+tid];
    for (int i=tid;i<4096;i+=128) Ws[(i>>6)*68+(i&63)]=W[i];
    if (tid<64) bs[tid]=b[tid];
    __syncthreads();
    for (int i=tid;i<8192;i+=128){
        int e=i>>6, f=i&63;
        Xs[e*65+f] = __ldg(&g_agg[(size_t)srcs[e]*64+f]) - __ldg(&g_m[(size_t)revs[e]*64+f]);
    }
    __syncthreads();
    u64 acc[4][8];
    gemm_core<4>(Xs,Ws,bs,w,lane,acc);
    #pragma unroll
    for (int j=0;j<4;j++){
        size_t erow=(base+lane+32*j)*64 + c0;
        float4* out=(float4*)&g_x[erow];
        #pragma unroll
        for (int q=0;q<4;q++){
            float2 a=unpack2(acc[j][2*q]), b2=unpack2(acc[j][2*q+1]);
            out[q]=make_float4(fmaxf(a.x,0.f),fmaxf(a.y,0.f),fmaxf(b2.x,0.f),fmaxf(b2.y,0.f));
        }
    }
}

// ---------------- fused gates + GRU (persistent, 512 threads, 2 fused walks, direct gmem output) ----------------
// smem: Xs[8320] Hs[8320] Wall[6*4352] Zs[16*512] bsm[256]
__global__ void __launch_bounds__(512,1) k_grufuse(
    const float* __restrict__ Wih, const float* __restrict__ bih,
    const float* __restrict__ Whh, const float* __restrict__ bhh)
{
    extern __shared__ float sm[];
    float* Xs  = sm;
    float* Hs  = sm + 8320;
    float* Wall= sm + 16640;
    float* Zs  = sm + 42752;
    float* bsm = sm + 50944;
    int tid=threadIdx.x, w=tid>>5, lane=tid&31;
    const int c0 = (w&7)*8;
    const int e0 = (w>>3)*64 + lane;   // edges e0, e0+32

    for (int i=tid;i<24576;i+=512){
        int m=i>>12, r=i&4095, c=r>>6, k=r&63;
        const float* Wsrc = (m<3)? Wih : Whh;
        int g = (m<3)? m : (m-3);
        Wall[m*4352 + k*68 + c] = Wsrc[(size_t)(g*64+c)*64 + k];
    }
    if (tid<64){
        bsm[tid]     = bih[tid]     + bhh[tid];       // r
        bsm[64+tid]  = bih[64+tid]  + bhh[64+tid];    // z
        bsm[128+tid] = bih[128+tid];                  // in
        bsm[192+tid] = bhh[128+tid];                  // hn
    }
    __syncthreads();

    for (int t=blockIdx.x; t<GRU_TILES; t+=gridDim.x){
        size_t base=(size_t)t*128;
        for (int i=tid;i<8192;i+=512){
            int e=i>>6, f=i&63;
            Xs[e*65+f]=__ldg(&g_x[base*64+i]);
            Hs[e*65+f]=__ldg(&g_message[base*64+i]);
        }
        __syncthreads();

        // ---- walk 1: fused r+z over X and H ----
        u64 ar[2][4], az[2][4];
        float rr[16];
        #pragma unroll
        for (int j=0;j<2;j++)
            #pragma unroll
            for (int q=0;q<4;q++){
                ar[j][q]=pack2(bsm[c0+2*q],    bsm[c0+2*q+1]);
                az[j][q]=pack2(bsm[64+c0+2*q], bsm[64+c0+2*q+1]);
            }
        gemm_rz(Xs,Hs,Wall,c0,e0,ar,az);
        #pragma unroll
        for (int j=0;j<2;j++)
            #pragma unroll
            for (int q=0;q<4;q++){
                float2 vr=unpack2(ar[j][q]);
                rr[j*8+2*q]=sigf(vr.x); rr[j*8+2*q+1]=sigf(vr.y);
                float2 vz=unpack2(az[j][q]);
                Zs[(j*8+2*q)*512+tid]  =sigf(vz.x);
                Zs[(j*8+2*q+1)*512+tid]=sigf(vz.y);
            }

        // ---- walk 2: fused n (X@Win, H@Whn) ----
        u64 accI[2][4], accH[2][4];
        #pragma unroll
        for (int j=0;j<2;j++)
            #pragma unroll
            for (int q=0;q<4;q++){
                accI[j][q]=pack2(bsm[128+c0+2*q],bsm[128+c0+2*q+1]);
                accH[j][q]=pack2(bsm[192+c0+2*q],bsm[192+c0+2*q+1]);
            }
        gemm_n(Xs,Hs,Wall,c0,e0,accI,accH);

        // combine + DIRECT gmem store (Hs never modified -> no pre-store barrier)
        #pragma unroll
        for (int j=0;j<2;j++){
            int e=e0+32*j;
            size_t erow=(base+e)*64 + c0;
            float4 o0, o1;
            {
                float2 iv=unpack2(accI[j][0]); float2 hv=unpack2(accH[j][0]);
                float nA=tanhf(iv.x + rr[j*8+0]*hv.x);
                float nB=tanhf(iv.y + rr[j*8+1]*hv.y);
                float zA=Zs[(j*8+0)*512+tid], zB=Zs[(j*8+1)*512+tid];
                o0.x=(1.f-zA)*nA+zA*Hs[e*65+c0+0];
                o0.y=(1.f-zB)*nB+zB*Hs[e*65+c0+1];
            }{
                float2 iv=unpack2(accI[j][1]); float2 hv=unpack2(accH[j][1]);
                float nA=tanhf(iv.x + rr[j*8+2]*hv.x);
                float nB=tanhf(iv.y + rr[j*8+3]*hv.y);
                float zA=Zs[(j*8+2)*512+tid], zB=Zs[(j*8+3)*512+tid];
                o0.z=(1.f-zA)*nA+zA*Hs[e*65+c0+2];
                o0.w=(1.f-zB)*nB+zB*Hs[e*65+c0+3];
            }{
                float2 iv=unpack2(accI[j][2]); float2 hv=unpack2(accH[j][2]);
                float nA=tanhf(iv.x + rr[j*8+4]*hv.x);
                float nB=tanhf(iv.y + rr[j*8+5]*hv.y);
                float zA=Zs[(j*8+4)*512+tid], zB=Zs[(j*8+5)*512+tid];
                o1.x=(1.f-zA)*nA+zA*Hs[e*65+c0+4];
                o1.y=(1.f-zB)*nB+zB*Hs[e*65+c0+5];
            }{
                float2 iv=unpack2(accI[j][3]); float2 hv=unpack2(accH[j][3]);
                float nA=tanhf(iv.x + rr[j*8+6]*hv.x);
                float nB=tanhf(iv.y + rr[j*8+7]*hv.y);
                float zA=Zs[(j*8+6)*512+tid], zB=Zs[(j*8+7)*512+tid];
                o1.z=(1.f-zA)*nA+zA*Hs[e*65+c0+6];
                o1.w=(1.f-zB)*nB+zB*Hs[e*65+c0+7];
            }
            float4* out=(float4*)&g_message[erow];
            out[0]=o0; out[1]=o1;
        }
        __syncthreads();   // all reads of Xs/Hs done before next tile's staging
    }
}

// ---------------- nodes_out ----------------
__global__ void __launch_bounds__(256) k_nodes_out(
    int iter, float* __restrict__ outM, float* __restrict__ outD,
    const float* __restrict__ Wagg, const float* __restrict__ bagg,
    const float* __restrict__ Wout)
{
    __shared__ float Wa[4096]; __shared__ float ba[64]; __shared__ float Wo[192];
    int tid=threadIdx.x;
    for (int i=tid;i<4096;i+=256) Wa[i]=Wagg[i];
    if (tid<64) ba[tid]=bagg[tid];
    for (int i=tid;i<192;i+=256) Wo[i]=Wout[i];
    __syncthreads();
    int n=blockIdx.x*256+tid;
    if (n>=NN) return;
    float af[64];
    const float4* ar=(const float4*)&g_agg[(size_t)n*64];
    #pragma unroll
    for (int q=0;q<16;q++){ float4 v=ar[q]; af[4*q]=v.x; af[4*q+1]=v.y; af[4*q+2]=v.z; af[4*q+3]=v.w; }
    u64 acc[32];
    #pragma unroll
    for (int j=0;j<32;j++) acc[j]=pack2(ba[2*j],ba[2*j+1]);
    #pragma unroll 4
    for (int k=0;k<64;k++){
        u64 x2=pack2(af[k],af[k]);
        const ulonglong2* wr=(const ulonglong2*)&Wa[k*64];
        #pragma unroll
        for (int q=0;q<16;q++){ ulonglong2 w=wr[q]; fma2(acc[2*q],x2,w.x); fma2(acc[2*q+1],x2,w.y); }
    }
    float l0=0.f,l1=0.f,l2=0.f;
    #pragma unroll
    for (int j=0;j<32;j++){
        float2 v=unpack2(acc[j]);
        float a0=fmaxf(v.x,0.f), a1=fmaxf(v.y,0.f);
        int k0=2*j, k1=2*j+1;
        l0 += a0*Wo[k0*3+0] + a1*Wo[k1*3+0];
        l1 += a0*Wo[k0*3+1] + a1*Wo[k1*3+1];
        l2 += a0*Wo[k0*3+2] + a1*Wo[k1*3+2];
    }
    l0=fmaxf(l0+g_nf_logit[n*3+0],0.f);
    l1=fmaxf(l1+g_nf_logit[n*3+1],0.f);
    l2=fmaxf(l2+g_nf_logit[n*3+2],0.f);
    float mx=fmaxf(l0,fmaxf(l1,l2));
    float e0=expf(l0-mx), e1=expf(l1-mx), e2=expf(l2-mx);
    float sum=e0+e1+e2, ls=logf(sum);
    size_t ob=(size_t)iter*((size_t)NN*3)+(size_t)n*3;
    outM[ob+0]=l0-mx-ls; outM[ob+1]=l1-mx-ls; outM[ob+2]=l2-mx-ls;
    float p2=e2/sum;
    if (iter>0){
        float d=fabsf(p2-g_prevp[n]);
        atomicMax((int*)&outD[iter-1], __float_as_int(d));
    }
    g_prevp[n]=p2;
}

// ---------------- host ----------------
extern "C" void kernel_launch(void* const* d_in, const int* in_sizes, int n_in,
                              void* d_out, int out_size)
{
    const int*   src  = (const int*)  d_in[0];
    const int*   tgt  = (const int*)  d_in[1];
    const int*   rev  = (const int*)  d_in[2];
    const float* raw  = (const float*)d_in[3];
    const float* prob = (const float*)d_in[4];
    const float* seed = (const float*)d_in[5];
    const float* W_node=(const float*)d_in[6],  *b_node=(const float*)d_in[7];
    const float* W_edge=(const float*)d_in[8],  *b_edge=(const float*)d_in[9];
    const float* W_init=(const float*)d_in[10], *b_init=(const float*)d_in[11];
    const float* W_aggr=(const float*)d_in[12], *b_aggr=(const float*)d_in[13];
    const float* W_out =(const float*)d_in[14], *b_out =(const float*)d_in[15];
    const float* W_me  =(const float*)d_in[16], *b_me  =(const float*)d_in[17];
    const float* W_mp  =(const float*)d_in[18], *b_mp  =(const float*)d_in[19];
    const float* W_ih  =(const float*)d_in[20], *W_hh  =(const float*)d_in[21];
    const float* b_ih  =(const float*)d_in[22], *b_hh  =(const float*)d_in[23];

    float* outM = (float*)d_out;
    float* outD = (float*)d_out + (size_t)5*NN*3;

    cudaFuncSetAttribute(k_edge_init, cudaFuncAttributeMaxDynamicSharedMemorySize, DSM);
    cudaFuncSetAttribute(k_me,        cudaFuncAttributeMaxDynamicSharedMemorySize, DSM);
    cudaFuncSetAttribute(k_mp,        cudaFuncAttributeMaxDynamicSharedMemorySize, DSM);
    cudaFuncSetAttribute(k_grufuse,   cudaFuncAttributeMaxDynamicSharedMemorySize, DSM_GRU);

    void *degPtr=0, *msgPtr=0, *mPtr=0;
    cudaGetSymbolAddress(&degPtr, g_deg);
    cudaGetSymbolAddress(&msgPtr, g_message);
    cudaGetSymbolAddress(&mPtr,   g_m);

    // launch order: #6 = k_edge_init (ncu -s 5 -c 1 captures it)
    cudaMemsetAsync(degPtr, 0, NN*sizeof(int));                                             // 1
    cudaMemsetAsync(outD, 0, 4*sizeof(float));                                              // 2
    k_hist<<<EE/256,256>>>(tgt);                                                            // 3
    k_scan<<<1,1024>>>();                                                                   // 4
    k_node<<<(NN+255)/256,256>>>(prob, seed, W_node, b_node, W_init, b_init, W_out, b_out); // 5
    k_edge_init<<<EE/128,128,DSM>>>(raw, src, W_edge, b_edge, W_init, W_me);                // 6 (captured)
    k_fill<<<EE/256,256>>>(tgt);                                                            // 7

    k_gather<<<NN/4,256>>>((const float*)msgPtr);
    k_nodes_out<<<(NN+255)/256,256>>>(0, outM, outD, W_aggr, b_aggr, W_out);

    for (int l=0; l<4; l++){
        k_me<<<EE/128,128,DSM>>>(W_me, b_me);
        k_gather<<<NN/4,256>>>((const float*)mPtr);
        k_mp<<<EE/128,128,DSM>>>(W_mp, b_mp, src, rev);
        k_grufuse<<<GRU_GRID,512,DSM_GRU>>>(W_ih, b_ih, W_hh, b_hh);
        k_gather<<<NN/4,256>>>((const float*)msgPtr);
        k_nodes_out<<<(NN+255)/256,256>>>(l+1, outM, outD, W_aggr, b_aggr, W_out);
    }
}

// round 16
// speedup vs baseline: 1.3036x; 1.1071x over previous
#include <cuda_runtime.h>

#define NN 50000
#define EE 800000

typedef unsigned long long u64;

// ---------------- f32x2 helpers ----------------
__device__ __forceinline__ void fma2(u64 &c, u64 a, u64 b){
    asm("fma.rn.f32x2 %0, %1, %2, %0;" : "+l"(c) : "l"(a), "l"(b));
}
__device__ __forceinline__ u64 pack2(float x, float y){
    u64 r; asm("mov.b64 %0, {%1, %2};" : "=l"(r) : "f"(x), "f"(y)); return r;
}
__device__ __forceinline__ float2 unpack2(u64 v){
    float2 r; asm("mov.b64 {%0, %1}, %2;" : "=f"(r.x), "=f"(r.y) : "l"(v)); return r;
}
__device__ __forceinline__ float sigf(float x){ return 1.f/(1.f+__expf(-x)); }

// ---------------- scratch ----------------
__device__ float g_node_pre[(size_t)NN*64];
__device__ float g_nf_logit[(size_t)NN*3];
__device__ float g_prevp[NN];
__device__ float g_agg[(size_t)NN*64];
__device__ float g_contrib[(size_t)EE*64];
__device__ float g_message[(size_t)EE*64];
__device__ float g_m[(size_t)EE*64];
__device__ int   g_deg[NN];
__device__ int   g_rowptr[NN+1];
__device__ int   g_cursor[NN];
__device__ int   g_eid[EE];

#define DSM 50944            // gemm64 kernels: Xs 8320 + Ws 4352 + bs 64 floats
// grufuse smem (floats): Xs 8320 + Hs 8320 + Wall 6*4096 + Wmp 4096 + Zs 8192 + bsm 256 + bmp 64 = 53824
#define DSM_GRU 215296
#define GRU_GRID 152
#define GRU_TILES 6250       // EE/128

// ---------------- GEMM core (register-lean, R11-proven): TE=128 ----------------
template<int NJ>
__device__ __forceinline__ void gemm_core(const float* Xs, const float* Ws, const float* bs,
                                          int w, int lane, u64 (&acc)[NJ][8])
{
    const int c0 = w*16;
    #pragma unroll
    for (int j=0;j<NJ;j++)
        #pragma unroll
        for (int q=0;q<8;q++) acc[j][q]=pack2(bs[c0+2*q],bs[c0+2*q+1]);
    #pragma unroll 2
    for (int k=0;k<64;k++){
        u64 x2[NJ];
        #pragma unroll
        for (int j=0;j<NJ;j++){
            float xk = Xs[(lane+32*j)*65 + k];
            x2[j] = pack2(xk,xk);
        }
        const ulonglong2* wp=(const ulonglong2*)(Ws + k*68 + c0);
        #pragma unroll
        for (int q=0;q<4;q++){
            ulonglong2 wv = wp[q];
            #pragma unroll
            for (int j=0;j<NJ;j++){
                fma2(acc[j][2*q],   x2[j], wv.x);
                fma2(acc[j][2*q+1], x2[j], wv.y);
            }
        }
    }
}

// ---------------- 8-col x 2-edge walk, stride-64 weights ----------------
__device__ __forceinline__ void gemm8x2s(const float* Xs, const float* Wm, int c0, int e0,
                                         u64 (&acc)[2][4])
{
    #pragma unroll 4
    for (int k=0;k<64;k++){
        u64 x2a, x2b;
        { float xk = Xs[e0*65 + k];       x2a = pack2(xk,xk); }
        { float xk = Xs[(e0+32)*65 + k];  x2b = pack2(xk,xk); }
        const ulonglong2* wp=(const ulonglong2*)(Wm + k*64 + c0);
        #pragma unroll
        for (int q=0;q<2;q++){
            ulonglong2 wv = wp[q];
            fma2(acc[0][2*q],   x2a, wv.x);
            fma2(acc[0][2*q+1], x2a, wv.y);
            fma2(acc[1][2*q],   x2b, wv.x);
            fma2(acc[1][2*q+1], x2b, wv.y);
        }
    }
}

// ---------------- fused rz walk (stride-64 weights) ----------------
__device__ __forceinline__ void gemm_rz(const float* Xs, const float* Hs, const float* Wall,
                                        int c0, int e0, u64 (&ar)[2][4], u64 (&az)[2][4])
{
    const float* Wxr = Wall + 0*4096;
    const float* Wxz = Wall + 1*4096;
    const float* Whr = Wall + 3*4096;
    const float* Whz = Wall + 4*4096;
    #pragma unroll 2
    for (int k=0;k<64;k++){
        u64 xa,xb,ha,hb;
        { float v=Xs[e0*65+k];      xa=pack2(v,v); }
        { float v=Xs[(e0+32)*65+k]; xb=pack2(v,v); }
        { float v=Hs[e0*65+k];      ha=pack2(v,v); }
        { float v=Hs[(e0+32)*65+k]; hb=pack2(v,v); }
        const ulonglong2* pxr=(const ulonglong2*)(Wxr + k*64 + c0);
        const ulonglong2* pxz=(const ulonglong2*)(Wxz + k*64 + c0);
        const ulonglong2* phr=(const ulonglong2*)(Whr + k*64 + c0);
        const ulonglong2* phz=(const ulonglong2*)(Whz + k*64 + c0);
        #pragma unroll
        for (int q=0;q<2;q++){
            ulonglong2 wxr=pxr[q], wxz=pxz[q];
            fma2(ar[0][2*q],xa,wxr.x); fma2(ar[0][2*q+1],xa,wxr.y);
            fma2(ar[1][2*q],xb,wxr.x); fma2(ar[1][2*q+1],xb,wxr.y);
            fma2(az[0][2*q],xa,wxz.x); fma2(az[0][2*q+1],xa,wxz.y);
            fma2(az[1][2*q],xb,wxz.x); fma2(az[1][2*q+1],xb,wxz.y);
            ulonglong2 whr=phr[q], whz=phz[q];
            fma2(ar[0][2*q],ha,whr.x); fma2(ar[0][2*q+1],ha,whr.y);
            fma2(ar[1][2*q],hb,whr.x); fma2(ar[1][2*q+1],hb,whr.y);
            fma2(az[0][2*q],ha,whz.x); fma2(az[0][2*q+1],ha,whz.y);
            fma2(az[1][2*q],hb,whz.x); fma2(az[1][2*q+1],hb,whz.y);
        }
    }
}

// ---------------- fused n walk (stride-64 weights) ----------------
__device__ __forceinline__ void gemm_n(const float* Xs, const float* Hs, const float* Wall,
                                       int c0, int e0, u64 (&ai)[2][4], u64 (&ah)[2][4])
{
    const float* Wxn = Wall + 2*4096;
    const float* Whn = Wall + 5*4096;
    #pragma unroll 2
    for (int k=0;k<64;k++){
        u64 xa,xb,ha,hb;
        { float v=Xs[e0*65+k];      xa=pack2(v,v); }
        { float v=Xs[(e0+32)*65+k]; xb=pack2(v,v); }
        { float v=Hs[e0*65+k];      ha=pack2(v,v); }
        { float v=Hs[(e0+32)*65+k]; hb=pack2(v,v); }
        const ulonglong2* pxn=(const ulonglong2*)(Wxn + k*64 + c0);
        const ulonglong2* phn=(const ulonglong2*)(Whn + k*64 + c0);
        #pragma unroll
        for (int q=0;q<2;q++){
            ulonglong2 wxn=pxn[q], whn=phn[q];
            fma2(ai[0][2*q],xa,wxn.x); fma2(ai[0][2*q+1],xa,wxn.y);
            fma2(ai[1][2*q],xb,wxn.x); fma2(ai[1][2*q+1],xb,wxn.y);
            fma2(ah[0][2*q],ha,whn.x); fma2(ah[0][2*q+1],ha,whn.y);
            fma2(ah[1][2*q],hb,whn.x); fma2(ah[1][2*q+1],hb,whn.y);
        }
    }
}

// ---------------- CSR build ----------------
__global__ void __launch_bounds__(256) k_hist(const int* __restrict__ tgt){
    int e=blockIdx.x*256+threadIdx.x;
    atomicAdd(&g_deg[tgt[e]],1);
}
__global__ void __launch_bounds__(1024) k_scan(){
    __shared__ int wsum[32];
    __shared__ int carry_s;
    int t=threadIdx.x, lane=t&31, wid=t>>5;
    if (t==0){ g_rowptr[0]=0; carry_s=0; }
    __syncthreads();
    for (int base=0; base<NN; base+=1024){
        int i=base+t;
        int v=(i<NN)? g_deg[i] : 0;
        int s=v;
        #pragma unroll
        for (int o=1;o<32;o<<=1){ int u=__shfl_up_sync(0xffffffffu,s,o); if(lane>=o) s+=u; }
        if (lane==31) wsum[wid]=s;
        __syncthreads();
        if (wid==0){
            int ws=wsum[lane];
            #pragma unroll
            for (int o=1;o<32;o<<=1){ int u=__shfl_up_sync(0xffffffffu,ws,o); if(lane>=o) ws+=u; }
            wsum[lane]=ws;
        }
        __syncthreads();
        int off=(wid>0)? wsum[wid-1] : 0;
        int inc=s+off+carry_s;
        if (i<NN){ g_rowptr[i+1]=inc; g_cursor[i]=inc-v; }
        __syncthreads();
        if (t==1023) carry_s=inc;
        __syncthreads();
    }
}
__global__ void __launch_bounds__(256) k_fill(const int* __restrict__ tgt){
    int e=blockIdx.x*256+threadIdx.x;
    int p=atomicAdd(&g_cursor[tgt[e]],1);
    g_eid[p]=e;
}

// ---------------- segment sum by gather ----------------
__global__ void __launch_bounds__(256) k_gather(const float* __restrict__ S){
    int node=blockIdx.x*4+(threadIdx.x>>6);
    int f=threadIdx.x&63;
    int s=g_rowptr[node], e=g_rowptr[node+1];
    float a=0.f;
    for (int i=s;i<e;i++){
        int eid=__ldg(&g_eid[i]);
        a += __ldg(&S[(size_t)eid*64+f]);
    }
    g_agg[(size_t)node*64+f]=a;
}

// ---------------- per-node precompute ----------------
__global__ void __launch_bounds__(256) k_node(
    const float* __restrict__ prob, const float* __restrict__ seed,
    const float* __restrict__ W_node, const float* __restrict__ b_node,
    const float* __restrict__ W_init, const float* __restrict__ b_init,
    const float* __restrict__ W_out,  const float* __restrict__ b_out)
{
    __shared__ float Wi[4096];
    __shared__ float Wn0[64], Wn1[64], bn[64], bi[64], Wo[192], bo[3];
    int tid = threadIdx.x;
    for (int i=tid;i<4096;i+=256) Wi[i]=W_init[i];
    if (tid<64){ Wn0[tid]=W_node[tid]; Wn1[tid]=W_node[64+tid]; bn[tid]=b_node[tid]; bi[tid]=b_init[tid]; }
    for (int i=tid;i<192;i+=256) Wo[i]=W_out[192+i];
    if (tid<3) bo[tid]=b_out[tid];
    __syncthreads();
    int n = blockIdx.x*256 + tid;
    if (n >= NN) return;
    float p = prob[n], s = seed[n];
    u64 acc[32];
    #pragma unroll
    for (int j=0;j<32;j++) acc[j]=pack2(bi[2*j],bi[2*j+1]);
    float l0=bo[0], l1=bo[1], l2=bo[2];
    #pragma unroll 4
    for (int k=0;k<64;k++){
        float nf = fmaxf(fmaf(p,Wn0[k],fmaf(s,Wn1[k],bn[k])), 0.f);
        u64 x2 = pack2(nf,nf);
        const ulonglong2* wr = (const ulonglong2*)&Wi[k*64];
        #pragma unroll
        for (int q=0;q<16;q++){ ulonglong2 w=wr[q]; fma2(acc[2*q],x2,w.x); fma2(acc[2*q+1],x2,w.y); }
        l0 = fmaf(nf,Wo[k*3],l0); l1 = fmaf(nf,Wo[k*3+1],l1); l2 = fmaf(nf,Wo[k*3+2],l2);
    }
    float4* outp = (float4*)&g_node_pre[(size_t)n*64];
    #pragma unroll
    for (int q=0;q<16;q++){ float2 a=unpack2(acc[2*q]); float2 b=unpack2(acc[2*q+1]); outp[q]=make_float4(a.x,a.y,b.x,b.y); }
    g_nf_logit[n*3]=l0; g_nf_logit[n*3+1]=l1; g_nf_logit[n*3+2]=l2;
}

// ---------------- edge init (TE=128, NJ=4, 4 blocks/SM, direct-store epilogues, Xs reused) ----------------
__global__ void __launch_bounds__(128,4) k_edge_init(
    const float* __restrict__ raw, const int* __restrict__ src,
    const float* __restrict__ W_edge, const float* __restrict__ b_edge,
    const float* __restrict__ W_init, const float* __restrict__ W_me)
{
    extern __shared__ float sm[];
    float* Xs=sm; float* Ws=sm+8320; float* bs=Ws+4352;
    __shared__ float we[64], be[64], rawv[128];
    __shared__ int srcs[128];
    int tid=threadIdx.x, w=tid>>5, lane=tid&31;
    size_t base=(size_t)blockIdx.x*128;
    const int c0=w*16;
    if (tid<64){ we[tid]=W_edge[tid]; be[tid]=b_edge[tid]; bs[tid]=0.f; }
    rawv[tid]=raw[base+tid]; srcs[tid]=src[base+tid];
    for (int i=tid;i<4096;i+=128) Ws[(i>>6)*68+(i&63)]=W_init[4096+i];
    __syncthreads();
    for (int i=tid;i<8192;i+=128){ int e=i>>6,f=i&63; Xs[e*65+f]=fmaxf(fmaf(rawv[e],we[f],be[f]),0.f); }
    __syncthreads();
    u64 acc[4][8];
    gemm_core<4>(Xs,Ws,bs,w,lane,acc);
    #pragma unroll
    for (int j=0;j<4;j++){
        int e=lane+32*j;
        size_t erow=(base+e)*64 + c0;
        const float4* np=(const float4*)&g_node_pre[(size_t)srcs[e]*64 + c0];
        float4* out=(float4*)&g_message[erow];
        #pragma unroll
        for (int q=0;q<4;q++){
            float2 a=unpack2(acc[j][2*q]), b=unpack2(acc[j][2*q+1]);
            float4 nv=np[q];
            out[q]=make_float4(fmaxf(a.x+nv.x,0.f),fmaxf(a.y+nv.y,0.f),
                               fmaxf(b.x+nv.z,0.f),fmaxf(b.y+nv.w,0.f));
        }
    }
    __syncthreads();
    for (int i=tid;i<4096;i+=128) Ws[(i>>6)*68+(i&63)]=W_me[4096+i];
    __syncthreads();
    gemm_core<4>(Xs,Ws,bs,w,lane,acc);
    #pragma unroll
    for (int j=0;j<4;j++){
        size_t erow=(base+lane+32*j)*64 + c0;
        float4* out=(float4*)&g_contrib[erow];
        #pragma unroll
        for (int q=0;q<4;q++){
            float2 a=unpack2(acc[j][2*q]), b=unpack2(acc[j][2*q+1]);
            out[q]=make_float4(a.x,a.y,b.x,b.y);
        }
    }
}

// ---------------- m = relu(message @ W_me[0:64] + contrib + b_me), direct store ----------------
__global__ void __launch_bounds__(128,4) k_me(const float* __restrict__ W, const float* __restrict__ b)
{
    extern __shared__ float sm[];
    float* Xs=sm; float* Ws=sm+8320; float* bs=Ws+4352;
    int tid=threadIdx.x, w=tid>>5, lane=tid&31;
    size_t base=(size_t)blockIdx.x*128;
    const int c0=w*16;
    for (int i=tid;i<4096;i+=128) Ws[(i>>6)*68+(i&63)]=W[i];
    if (tid<64) bs[tid]=b[tid];
    for (int i=tid;i<8192;i+=128) Xs[(i>>6)*65+(i&63)]=g_message[base*64+i];
    __syncthreads();
    u64 acc[4][8];
    gemm_core<4>(Xs,Ws,bs,w,lane,acc);
    #pragma unroll
    for (int j=0;j<4;j++){
        size_t erow=(base+lane+32*j)*64 + c0;
        const float4* ct=(const float4*)&g_contrib[erow];
        float4* out=(float4*)&g_m[erow];
        #pragma unroll
        for (int q=0;q<4;q++){
            float2 a=unpack2(acc[j][2*q]), b2=unpack2(acc[j][2*q+1]);
            float4 c=ct[q];
            out[q]=make_float4(fmaxf(a.x+c.x,0.f),fmaxf(a.y+c.y,0.f),
                               fmaxf(b2.x+c.z,0.f),fmaxf(b2.y+c.w,0.f));
        }
    }
}

// ---------------- fused x-compute + gates + GRU (persistent, 512 threads) ----------------
// smem: Xs[8320] Hs[8320] Wall[6*4096] Wmp[4096] Zs[8192] bsm[256] bmp[64]
__global__ void __launch_bounds__(512,1) k_grufuse(
    const int* __restrict__ src, const int* __restrict__ rev,
    const float* __restrict__ Wmpg, const float* __restrict__ bmpg,
    const float* __restrict__ Wih, const float* __restrict__ bih,
    const float* __restrict__ Whh, const float* __restrict__ bhh)
{
    extern __shared__ float sm[];
    float* Xs  = sm;
    float* Hs  = sm + 8320;
    float* Wall= sm + 16640;
    float* Wmp = sm + 41216;
    float* Zs  = sm + 45312;
    float* bsm = sm + 53504;
    float* bmp = sm + 53760;
    int tid=threadIdx.x, w=tid>>5, lane=tid&31;
    const int c0 = (w&7)*8;
    const int e0 = (w>>3)*64 + lane;   // edges e0, e0+32

    for (int i=tid;i<24576;i+=512){
        int m=i>>12, r=i&4095, c=r>>6, k=r&63;
        const float* Wsrc = (m<3)? Wih : Whh;
        int g = (m<3)? m : (m-3);
        Wall[m*4096 + k*64 + c] = Wsrc[(size_t)(g*64+c)*64 + k];
    }
    for (int i=tid;i<4096;i+=512) Wmp[i]=Wmpg[i];
    if (tid<64){
        bsm[tid]     = bih[tid]     + bhh[tid];       // r
        bsm[64+tid]  = bih[64+tid]  + bhh[64+tid];    // z
        bsm[128+tid] = bih[128+tid];                  // in
        bsm[192+tid] = bhh[128+tid];                  // hn
        bmp[tid]     = bmpg[tid];
    }
    __syncthreads();

    for (int t=blockIdx.x; t<GRU_TILES; t+=gridDim.x){
        size_t base=(size_t)t*128;
        // stage In = agg[src] - m[rev] into Xs ; H into Hs
        for (int i=tid;i<8192;i+=512){
            int e=i>>6, f=i&63;
            int sn=__ldg(&src[base+e]);
            int re=__ldg(&rev[base+e]);
            Xs[e*65+f]=__ldg(&g_agg[(size_t)sn*64+f]) - __ldg(&g_m[(size_t)re*64+f]);
            Hs[e*65+f]=__ldg(&g_message[base*64+i]);
        }
        __syncthreads();

        // ---- mp walk: x = relu(In @ Wmp + bmp), computed to regs then written in-place ----
        {
            u64 am[2][4];
            #pragma unroll
            for (int j=0;j<2;j++)
                #pragma unroll
                for (int q=0;q<4;q++) am[j][q]=pack2(bmp[c0+2*q],bmp[c0+2*q+1]);
            gemm8x2s(Xs, Wmp, c0, e0, am);
            __syncthreads();   // all reads of Xs (In) complete
            #pragma unroll
            for (int j=0;j<2;j++){
                int e=e0+32*j;
                #pragma unroll
                for (int q=0;q<4;q++){
                    float2 v=unpack2(am[j][q]);
                    Xs[e*65+c0+2*q]  =fmaxf(v.x,0.f);
                    Xs[e*65+c0+2*q+1]=fmaxf(v.y,0.f);
                }
            }
        }
        __syncthreads();       // Xs now holds x for all threads

        // ---- walk 1: fused r+z over X and H ----
        u64 ar[2][4], az[2][4];
        float rr[16];
        #pragma unroll
        for (int j=0;j<2;j++)
            #pragma unroll
            for (int q=0;q<4;q++){
                ar[j][q]=pack2(bsm[c0+2*q],    bsm[c0+2*q+1]);
                az[j][q]=pack2(bsm[64+c0+2*q], bsm[64+c0+2*q+1]);
            }
        gemm_rz(Xs,Hs,Wall,c0,e0,ar,az);
        #pragma unroll
        for (int j=0;j<2;j++)
            #pragma unroll
            for (int q=0;q<4;q++){
                float2 vr=unpack2(ar[j][q]);
                rr[j*8+2*q]=sigf(vr.x); rr[j*8+2*q+1]=sigf(vr.y);
                float2 vz=unpack2(az[j][q]);
                Zs[(j*8+2*q)*512+tid]  =sigf(vz.x);
                Zs[(j*8+2*q+1)*512+tid]=sigf(vz.y);
            }

        // ---- walk 2: fused n (X@Win, H@Whn) ----
        u64 accI[2][4], accH[2][4];
        #pragma unroll
        for (int j=0;j<2;j++)
            #pragma unroll
            for (int q=0;q<4;q++){
                accI[j][q]=pack2(bsm[128+c0+2*q],bsm[128+c0+2*q+1]);
                accH[j][q]=pack2(bsm[192+c0+2*q],bsm[192+c0+2*q+1]);
            }
        gemm_n(Xs,Hs,Wall,c0,e0,accI,accH);

        // combine + DIRECT gmem store (Hs never modified)
        #pragma unroll
        for (int j=0;j<2;j++){
            int e=e0+32*j;
            size_t erow=(base+e)*64 + c0;
            float4 o0, o1;
            {
                float2 iv=unpack2(accI[j][0]); float2 hv=unpack2(accH[j][0]);
                float nA=tanhf(iv.x + rr[j*8+0]*hv.x);
                float nB=tanhf(iv.y + rr[j*8+1]*hv.y);
                float zA=Zs[(j*8+0)*512+tid], zB=Zs[(j*8+1)*512+tid];
                o0.x=(1.f-zA)*nA+zA*Hs[e*65+c0+0];
                o0.y=(1.f-zB)*nB+zB*Hs[e*65+c0+1];
            }{
                float2 iv=unpack2(accI[j][1]); float2 hv=unpack2(accH[j][1]);
                float nA=tanhf(iv.x + rr[j*8+2]*hv.x);
                float nB=tanhf(iv.y + rr[j*8+3]*hv.y);
                float zA=Zs[(j*8+2)*512+tid], zB=Zs[(j*8+3)*512+tid];
                o0.z=(1.f-zA)*nA+zA*Hs[e*65+c0+2];
                o0.w=(1.f-zB)*nB+zB*Hs[e*65+c0+3];
            }{
                float2 iv=unpack2(accI[j][2]); float2 hv=unpack2(accH[j][2]);
                float nA=tanhf(iv.x + rr[j*8+4]*hv.x);
                float nB=tanhf(iv.y + rr[j*8+5]*hv.y);
                float zA=Zs[(j*8+4)*512+tid], zB=Zs[(j*8+5)*512+tid];
                o1.x=(1.f-zA)*nA+zA*Hs[e*65+c0+4];
                o1.y=(1.f-zB)*nB+zB*Hs[e*65+c0+5];
            }{
                float2 iv=unpack2(accI[j][3]); float2 hv=unpack2(accH[j][3]);
                float nA=tanhf(iv.x + rr[j*8+6]*hv.x);
                float nB=tanhf(iv.y + rr[j*8+7]*hv.y);
                float zA=Zs[(j*8+6)*512+tid], zB=Zs[(j*8+7)*512+tid];
                o1.z=(1.f-zA)*nA+zA*Hs[e*65+c0+6];
                o1.w=(1.f-zB)*nB+zB*Hs[e*65+c0+7];
            }
            float4* out=(float4*)&g_message[erow];
            out[0]=o0; out[1]=o1;
        }
        __syncthreads();   // all reads of Xs/Hs done before next tile's staging
    }
}

// ---------------- nodes_out ----------------
__global__ void __launch_bounds__(256) k_nodes_out(
    int iter, float* __restrict__ outM, float* __restrict__ outD,
    const float* __restrict__ Wagg, const float* __restrict__ bagg,
    const float* __restrict__ Wout)
{
    __shared__ float Wa[4096]; __shared__ float ba[64]; __shared__ float Wo[192];
    int tid=threadIdx.x;
    for (int i=tid;i<4096;i+=256) Wa[i]=Wagg[i];
    if (tid<64) ba[tid]=bagg[tid];
    for (int i=tid;i<192;i+=256) Wo[i]=Wout[i];
    __syncthreads();
    int n=blockIdx.x*256+tid;
    if (n>=NN) return;
    float af[64];
    const float4* ar=(const float4*)&g_agg[(size_t)n*64];
    #pragma unroll
    for (int q=0;q<16;q++){ float4 v=ar[q]; af[4*q]=v.x; af[4*q+1]=v.y; af[4*q+2]=v.z; af[4*q+3]=v.w; }
    u64 acc[32];
    #pragma unroll
    for (int j=0;j<32;j++) acc[j]=pack2(ba[2*j],ba[2*j+1]);
    #pragma unroll 4
    for (int k=0;k<64;k++){
        u64 x2=pack2(af[k],af[k]);
        const ulonglong2* wr=(const ulonglong2*)&Wa[k*64];
        #pragma unroll
        for (int q=0;q<16;q++){ ulonglong2 w=wr[q]; fma2(acc[2*q],x2,w.x); fma2(acc[2*q+1],x2,w.y); }
    }
    float l0=0.f,l1=0.f,l2=0.f;
    #pragma unroll
    for (int j=0;j<32;j++){
        float2 v=unpack2(acc[j]);
        float a0=fmaxf(v.x,0.f), a1=fmaxf(v.y,0.f);
        int k0=2*j, k1=2*j+1;
        l0 += a0*Wo[k0*3+0] + a1*Wo[k1*3+0];
        l1 += a0*Wo[k0*3+1] + a1*Wo[k1*3+1];
        l2 += a0*Wo[k0*3+2] + a1*Wo[k1*3+2];
    }
    l0=fmaxf(l0+g_nf_logit[n*3+0],0.f);
    l1=fmaxf(l1+g_nf_logit[n*3+1],0.f);
    l2=fmaxf(l2+g_nf_logit[n*3+2],0.f);
    float mx=fmaxf(l0,fmaxf(l1,l2));
    float e0=expf(l0-mx), e1=expf(l1-mx), e2=expf(l2-mx);
    float sum=e0+e1+e2, ls=logf(sum);
    size_t ob=(size_t)iter*((size_t)NN*3)+(size_t)n*3;
    outM[ob+0]=l0-mx-ls; outM[ob+1]=l1-mx-ls; outM[ob+2]=l2-mx-ls;
    float p2=e2/sum;
    if (iter>0){
        float d=fabsf(p2-g_prevp[n]);
        atomicMax((int*)&outD[iter-1], __float_as_int(d));
    }
    g_prevp[n]=p2;
}

// ---------------- host ----------------
extern "C" void kernel_launch(void* const* d_in, const int* in_sizes, int n_in,
                              void* d_out, int out_size)
{
    const int*   src  = (const int*)  d_in[0];
    const int*   tgt  = (const int*)  d_in[1];
    const int*   rev  = (const int*)  d_in[2];
    const float* raw  = (const float*)d_in[3];
    const float* prob = (const float*)d_in[4];
    const float* seed = (const float*)d_in[5];
    const float* W_node=(const float*)d_in[6],  *b_node=(const float*)d_in[7];
    const float* W_edge=(const float*)d_in[8],  *b_edge=(const float*)d_in[9];
    const float* W_init=(const float*)d_in[10], *b_init=(const float*)d_in[11];
    const float* W_aggr=(const float*)d_in[12], *b_aggr=(const float*)d_in[13];
    const float* W_out =(const float*)d_in[14], *b_out =(const float*)d_in[15];
    const float* W_me  =(const float*)d_in[16], *b_me  =(const float*)d_in[17];
    const float* W_mp  =(const float*)d_in[18], *b_mp  =(const float*)d_in[19];
    const float* W_ih  =(const float*)d_in[20], *W_hh  =(const float*)d_in[21];
    const float* b_ih  =(const float*)d_in[22], *b_hh  =(const float*)d_in[23];

    float* outM = (float*)d_out;
    float* outD = (float*)d_out + (size_t)5*NN*3;

    cudaFuncSetAttribute(k_edge_init, cudaFuncAttributeMaxDynamicSharedMemorySize, DSM);
    cudaFuncSetAttribute(k_me,        cudaFuncAttributeMaxDynamicSharedMemorySize, DSM);
    cudaFuncSetAttribute(k_grufuse,   cudaFuncAttributeMaxDynamicSharedMemorySize, DSM_GRU);

    void *degPtr=0, *msgPtr=0, *mPtr=0;
    cudaGetSymbolAddress(&degPtr, g_deg);
    cudaGetSymbolAddress(&msgPtr, g_message);
    cudaGetSymbolAddress(&mPtr,   g_m);

    // launch order: #6 = k_edge_init (ncu -s 5 -c 1 captures it)
    cudaMemsetAsync(degPtr, 0, NN*sizeof(int));                                             // 1
    cudaMemsetAsync(outD, 0, 4*sizeof(float));                                              // 2
    k_hist<<<EE/256,256>>>(tgt);                                                            // 3
    k_scan<<<1,1024>>>();                                                                   // 4
    k_node<<<(NN+255)/256,256>>>(prob, seed, W_node, b_node, W_init, b_init, W_out, b_out); // 5
    k_edge_init<<<EE/128,128,DSM>>>(raw, src, W_edge, b_edge, W_init, W_me);                // 6 (captured)
    k_fill<<<EE/256,256>>>(tgt);                                                            // 7

    k_gather<<<NN/4,256>>>((const float*)msgPtr);
    k_nodes_out<<<(NN+255)/256,256>>>(0, outM, outD, W_aggr, b_aggr, W_out);

    for (int l=0; l<4; l++){
        k_me<<<EE/128,128,DSM>>>(W_me, b_me);
        k_gather<<<NN/4,256>>>((const float*)mPtr);
        k_grufuse<<<GRU_GRID,512,DSM_GRU>>>(src, rev, W_mp, b_mp, W_ih, b_ih, W_hh, b_hh);
        k_gather<<<NN/4,256>>>((const float*)msgPtr);
        k_nodes_out<<<(NN+255)/256,256>>>(l+1, outM, outD, W_aggr, b_aggr, W_out);
    }
}